// round 1
// baseline (speedup 1.0000x reference)
#include <cuda_runtime.h>
#include <math.h>

#define HDIM 250
#define NLAYERS 7         // 1 input + 6 hidden
#define NHID (NLAYERS-1)  // 6 hidden weight matrices
#define SPB 2             // samples per block
#define NTHREADS 256

// channels: 0=val 1=dx 2=dy 3=dt 4=dxx 5=dyy 6=dxy (7 padded to 8 for LDS.128)

__global__ __launch_bounds__(NTHREADS)
void pinn_kernel(const float* __restrict__ x,
                 const float* __restrict__ y,
                 const float* __restrict__ t,
                 const float* __restrict__ W_in,
                 const float* __restrict__ b_in,
                 const float* __restrict__ W_h,
                 const float* __restrict__ b_h,
                 const float* __restrict__ W_out,
                 const float* __restrict__ b_out,
                 const float* __restrict__ act,
                 float* __restrict__ out,
                 int N)
{
    __shared__ float hs[SPB][HDIM][8];
    __shared__ float zsh[SPB][4][8];
    __shared__ float cs[NLAYERS];

    const int j = threadIdx.x;
    const int n0 = blockIdx.x * SPB;

    if (j < NLAYERS) cs[j] = 10.0f * act[j];   // N_ACT * act_coeff
    __syncthreads();

    // ---------------- input layer ----------------
    if (j < HDIM) {
        const float w0 = W_in[j];
        const float w1 = W_in[HDIM + j];
        const float w2 = W_in[2*HDIM + j];
        const float bj = b_in[j];
        const float c  = cs[0];
        #pragma unroll
        for (int s = 0; s < SPB; ++s) {
            int n = n0 + s;
            float px = 0.f, py = 0.f, pt = 0.f;
            if (n < N) { px = x[n]; py = y[n]; pt = t[n]; }
            float z  = px*w0 + py*w1 + pt*w2 + bj;
            float f  = tanhf(c*z);
            float d  = c*(1.0f - f*f);
            float fx = d*w0, fy = d*w1, ft = d*w2;
            float m2cf = -2.0f*c*f;
            // second derivs of z are zero at the input layer
            float fxx = m2cf*fx*w0;
            float fyy = m2cf*fy*w1;
            float fxy = m2cf*fy*w0;
            hs[s][j][0]=f;   hs[s][j][1]=fx;  hs[s][j][2]=fy;  hs[s][j][3]=ft;
            hs[s][j][4]=fxx; hs[s][j][5]=fyy; hs[s][j][6]=fxy; hs[s][j][7]=0.f;
        }
    }
    __syncthreads();

    // ---------------- hidden layers ----------------
    for (int l = 0; l < NHID; ++l) {
        const float* __restrict__ W = W_h + (size_t)l*HDIM*HDIM;
        float a00=0.f,a01=0.f,a02=0.f,a03=0.f,a04=0.f,a05=0.f,a06=0.f;
        float a10=0.f,a11=0.f,a12=0.f,a13=0.f,a14=0.f,a15=0.f,a16=0.f;
        if (j < HDIM) {
            #pragma unroll 5
            for (int i = 0; i < HDIM; ++i) {
                float w = __ldg(&W[i*HDIM + j]);
                float4 h0a = *reinterpret_cast<const float4*>(&hs[0][i][0]);
                float4 h0b = *reinterpret_cast<const float4*>(&hs[0][i][4]);
                float4 h1a = *reinterpret_cast<const float4*>(&hs[1][i][0]);
                float4 h1b = *reinterpret_cast<const float4*>(&hs[1][i][4]);
                a00 += h0a.x*w; a01 += h0a.y*w; a02 += h0a.z*w; a03 += h0a.w*w;
                a04 += h0b.x*w; a05 += h0b.y*w; a06 += h0b.z*w;
                a10 += h1a.x*w; a11 += h1a.y*w; a12 += h1a.z*w; a13 += h1a.w*w;
                a14 += h1b.x*w; a15 += h1b.y*w; a16 += h1b.z*w;
            }
        }
        __syncthreads();
        if (j < HDIM) {
            const float bj = b_h[l*HDIM + j];
            const float c  = cs[l+1];
            {
                float z = a00 + bj;
                float f = tanhf(c*z);
                float d = c*(1.0f - f*f);
                float fx = d*a01, fy = d*a02, ft = d*a03;
                float m2cf = -2.0f*c*f;
                float fxx = d*a04 + m2cf*fx*a01;
                float fyy = d*a05 + m2cf*fy*a02;
                float fxy = d*a06 + m2cf*fy*a01;
                hs[0][j][0]=f;   hs[0][j][1]=fx;  hs[0][j][2]=fy;  hs[0][j][3]=ft;
                hs[0][j][4]=fxx; hs[0][j][5]=fyy; hs[0][j][6]=fxy;
            }
            {
                float z = a10 + bj;
                float f = tanhf(c*z);
                float d = c*(1.0f - f*f);
                float fx = d*a11, fy = d*a12, ft = d*a13;
                float m2cf = -2.0f*c*f;
                float fxx = d*a14 + m2cf*fx*a11;
                float fyy = d*a15 + m2cf*fy*a12;
                float fxy = d*a16 + m2cf*fy*a11;
                hs[1][j][0]=f;   hs[1][j][1]=fx;  hs[1][j][2]=fy;  hs[1][j][3]=ft;
                hs[1][j][4]=fxx; hs[1][j][5]=fyy; hs[1][j][6]=fxy;
            }
        }
        __syncthreads();
    }

    // ---------------- output layer: 2 samples * 4 outputs * 7 channels = 56 dots ----------------
    if (j < 2*28) {
        int s = j / 28;
        int k = j % 28;
        int o = k / 7;
        int c = k % 7;
        float s0 = 0.f, s1 = 0.f;
        #pragma unroll 2
        for (int i = 0; i < HDIM; i += 2) {
            s0 += hs[s][i  ][c] * __ldg(&W_out[(i  )*4 + o]);
            s1 += hs[s][i+1][c] * __ldg(&W_out[(i+1)*4 + o]);
        }
        float acc = s0 + s1;
        if (c == 0) acc += b_out[o];
        zsh[s][o][c] = acc;
    }
    __syncthreads();

    // ---------------- residual assembly ----------------
    if (j < SPB) {
        int s = j;
        int n = n0 + s;
        if (n < N) {
            float u   = zsh[s][0][0], ux = zsh[s][0][1], uy = zsh[s][0][2], ut = zsh[s][0][3];
            float uxx = zsh[s][0][4], uyy = zsh[s][0][5];
            float v   = zsh[s][1][0], vx = zsh[s][1][1], vy = zsh[s][1][2], vt = zsh[s][1][3];
            float vxx = zsh[s][1][4], vyy = zsh[s][1][5];
            float pe  = expf(zsh[s][2][0]);
            float p_x = pe * zsh[s][2][1];
            float p_y = pe * zsh[s][2][2];
            float z3  = zsh[s][3][0];
            float aa  = 1.0f / (1.0f + expf(-z3));
            float da  = aa * (1.0f - aa);
            float zax = zsh[s][3][1], zay = zsh[s][3][2], zat = zsh[s][3][3];
            float ax  = da * zax, ay = da * zay, at = da * zat;
            float om  = da * (1.0f - 2.0f*aa);
            float axx = om*zax*zax + da*zsh[s][3][4];
            float ayy = om*zay*zay + da*zsh[s][3][5];
            float axy = om*zax*zay + da*zsh[s][3][6];

            const float MU1 = 1.0f, MU2 = 10.0f;
            const float RHO1 = 100.0f, RHO2 = 1000.0f, RHO_REF = 1000.0f;
            const float ONE_WE = 24.5f / (RHO_REF * 1.0f * 0.5f);   // 0.049
            const float ONE_FR = 0.98f * 0.5f / 1.0f;               // 0.49
            const float RE_DEN = RHO_REF * 1.0f * 0.5f;             // 500
            const float EPSC = 2.2204460492503131e-16f;

            float mu  = MU2 + (MU1 - MU2)*aa;
            float mux = (MU1 - MU2)*ax;
            float muy = (MU1 - MU2)*ay;
            float rho = RHO2 + (RHO1 - RHO2)*aa;
            float g   = sqrtf(ax*ax + ay*ay + EPSC);
            float g3  = g*g*g;
            float curv = -((axx + ayy)/g - (ax*ax*axx + ay*ay*ayy + 2.0f*ax*ay*axy)/g3);
            float oRe  = mu  / RE_DEN;
            float oRex = mux / RE_DEN;
            float oRey = muy / RE_DEN;
            float rr   = rho / RHO_REF;

            float PDE_m = ux + vy;
            float PDE_a = at + u*ax + v*ay;
            float PDE_u = (ut + u*ux + v*uy)*rr + p_x - ONE_WE*curv*ax
                        - oRe*(uxx + uyy) - 2.0f*oRex*ux - oRey*(uy + vx);
            float PDE_v = (vt + u*vx + v*vy)*rr + p_y - ONE_WE*curv*ay
                        - oRe*(vxx + vyy) - rr*ONE_FR - 2.0f*oRey*vy - oRex*(uy + vx);

            out[0*N + n] = PDE_m;
            out[1*N + n] = PDE_u;
            out[2*N + n] = PDE_v;
            out[3*N + n] = PDE_a;
        }
    }
}

extern "C" void kernel_launch(void* const* d_in, const int* in_sizes, int n_in,
                              void* d_out, int out_size)
{
    const float* x     = (const float*)d_in[0];
    const float* y     = (const float*)d_in[1];
    const float* t     = (const float*)d_in[2];
    const float* W_in  = (const float*)d_in[3];
    const float* b_in  = (const float*)d_in[4];
    const float* W_h   = (const float*)d_in[5];
    const float* b_h   = (const float*)d_in[6];
    const float* W_out = (const float*)d_in[7];
    const float* b_out = (const float*)d_in[8];
    const float* act   = (const float*)d_in[9];
    float* out = (float*)d_out;
    int N = in_sizes[0];
    int blocks = (N + SPB - 1) / SPB;
    pinn_kernel<<<blocks, NTHREADS>>>(x, y, t, W_in, b_in, W_h, b_h,
                                      W_out, b_out, act, out, N);
}

// round 2
// speedup vs baseline: 1.3946x; 1.3946x over previous
#include <cuda_runtime.h>
#include <math.h>

#define HDIM 250
#define HALF 125          // HDIM/2, column stride per thread
#define NLAYERS 7         // 1 input + 6 hidden
#define NHID (NLAYERS-1)  // 6 hidden weight matrices
#define SPB 2             // samples per block
#define NTHREADS 128

// smem channel layout per unit: pairs (val,dx)(dy,dt)(dxx,dyy)(dxy,0) -> 8 floats

__device__ __forceinline__ void fma2(unsigned long long &d,
                                     unsigned long long a,
                                     unsigned long long b) {
    asm("fma.rn.f32x2 %0, %1, %2, %0;" : "+l"(d) : "l"(a), "l"(b));
}
__device__ __forceinline__ unsigned long long pack2(float lo, float hi) {
    unsigned long long r;
    asm("mov.b64 %0, {%1, %2};" : "=l"(r) : "f"(lo), "f"(hi));
    return r;
}
__device__ __forceinline__ void unpack2(float &lo, float &hi, unsigned long long v) {
    asm("mov.b64 {%0, %1}, %2;" : "=f"(lo), "=f"(hi) : "l"(v));
}

__global__ __launch_bounds__(NTHREADS)
void pinn_kernel(const float* __restrict__ x,
                 const float* __restrict__ y,
                 const float* __restrict__ t,
                 const float* __restrict__ W_in,
                 const float* __restrict__ b_in,
                 const float* __restrict__ W_h,
                 const float* __restrict__ b_h,
                 const float* __restrict__ W_out,
                 const float* __restrict__ b_out,
                 const float* __restrict__ act,
                 float* __restrict__ out,
                 int N)
{
    __shared__ float hs[SPB][HDIM][8];
    __shared__ float zsh[SPB][4][8];
    __shared__ float cs[NLAYERS];

    const int j = threadIdx.x;
    const int n0 = blockIdx.x * SPB;

    if (j < NLAYERS) cs[j] = 10.0f * act[j];   // N_ACT * act_coeff
    __syncthreads();

    // ---------------- input layer: thread j handles columns j and j+125 ----------------
    if (j < HALF) {
        const float c = cs[0];
        #pragma unroll
        for (int cc = 0; cc < 2; ++cc) {
            const int col = j + cc*HALF;
            const float w0 = W_in[col];
            const float w1 = W_in[HDIM + col];
            const float w2 = W_in[2*HDIM + col];
            const float bj = b_in[col];
            #pragma unroll
            for (int s = 0; s < SPB; ++s) {
                int n = n0 + s;
                float px = 0.f, py = 0.f, pt = 0.f;
                if (n < N) { px = x[n]; py = y[n]; pt = t[n]; }
                float z  = px*w0 + py*w1 + pt*w2 + bj;
                float f  = tanhf(c*z);
                float d  = c*(1.0f - f*f);
                float fx = d*w0, fy = d*w1, ft = d*w2;
                float m2cf = -2.0f*c*f;
                float fxx = m2cf*fx*w0;
                float fyy = m2cf*fy*w1;
                float fxy = m2cf*fy*w0;
                hs[s][col][0]=f;   hs[s][col][1]=fx;  hs[s][col][2]=fy;  hs[s][col][3]=ft;
                hs[s][col][4]=fxx; hs[s][col][5]=fyy; hs[s][col][6]=fxy; hs[s][col][7]=0.f;
            }
        }
    }
    __syncthreads();

    // ---------------- hidden layers ----------------
    for (int l = 0; l < NHID; ++l) {
        const float* __restrict__ W = W_h + (size_t)l*HDIM*HDIM;
        // acc[s][col][pair] as named u64 regs (f32x2 packed)
        unsigned long long a000=0,a001=0,a002=0,a003=0;  // s0 col0
        unsigned long long a010=0,a011=0,a012=0,a013=0;  // s0 col1
        unsigned long long a100=0,a101=0,a102=0,a103=0;  // s1 col0
        unsigned long long a110=0,a111=0,a112=0,a113=0;  // s1 col1
        if (j < HALF) {
            #pragma unroll 2
            for (int i = 0; i < HDIM; ++i) {
                float w0 = __ldg(&W[i*HDIM + j]);
                float w1 = __ldg(&W[i*HDIM + j + HALF]);
                unsigned long long W0 = pack2(w0, w0);
                unsigned long long W1 = pack2(w1, w1);
                ulonglong2 h0a = *reinterpret_cast<const ulonglong2*>(&hs[0][i][0]);
                ulonglong2 h0b = *reinterpret_cast<const ulonglong2*>(&hs[0][i][4]);
                ulonglong2 h1a = *reinterpret_cast<const ulonglong2*>(&hs[1][i][0]);
                ulonglong2 h1b = *reinterpret_cast<const ulonglong2*>(&hs[1][i][4]);
                fma2(a000, h0a.x, W0); fma2(a001, h0a.y, W0);
                fma2(a002, h0b.x, W0); fma2(a003, h0b.y, W0);
                fma2(a010, h0a.x, W1); fma2(a011, h0a.y, W1);
                fma2(a012, h0b.x, W1); fma2(a013, h0b.y, W1);
                fma2(a100, h1a.x, W0); fma2(a101, h1a.y, W0);
                fma2(a102, h1b.x, W0); fma2(a103, h1b.y, W0);
                fma2(a110, h1a.x, W1); fma2(a111, h1a.y, W1);
                fma2(a112, h1b.x, W1); fma2(a113, h1b.y, W1);
            }
        }
        __syncthreads();
        if (j < HALF) {
            const float c = cs[l+1];
            #pragma unroll
            for (int s = 0; s < SPB; ++s) {
                #pragma unroll
                for (int cc = 0; cc < 2; ++cc) {
                    const int col = j + cc*HALF;
                    const float bj = b_h[l*HDIM + col];
                    unsigned long long p0, p1, p2, p3;
                    if (s == 0 && cc == 0) { p0=a000; p1=a001; p2=a002; p3=a003; }
                    else if (s == 0)       { p0=a010; p1=a011; p2=a012; p3=a013; }
                    else if (cc == 0)      { p0=a100; p1=a101; p2=a102; p3=a103; }
                    else                   { p0=a110; p1=a111; p2=a112; p3=a113; }
                    float zv, zx, zy, zt, zxx, zyy, zxy, zpad;
                    unpack2(zv, zx, p0);
                    unpack2(zy, zt, p1);
                    unpack2(zxx, zyy, p2);
                    unpack2(zxy, zpad, p3);
                    float z = zv + bj;
                    float f = tanhf(c*z);
                    float d = c*(1.0f - f*f);
                    float fx = d*zx, fy = d*zy, ft = d*zt;
                    float m2cf = -2.0f*c*f;
                    float fxx = d*zxx + m2cf*fx*zx;
                    float fyy = d*zyy + m2cf*fy*zy;
                    float fxy = d*zxy + m2cf*fy*zx;
                    hs[s][col][0]=f;   hs[s][col][1]=fx;  hs[s][col][2]=fy;  hs[s][col][3]=ft;
                    hs[s][col][4]=fxx; hs[s][col][5]=fyy; hs[s][col][6]=fxy;
                }
            }
        }
        __syncthreads();
    }

    // ---------------- output layer: 2 samples * 4 outputs * 7 channels = 56 dots ----------------
    if (j < 2*28) {
        int s = j / 28;
        int k = j % 28;
        int o = k / 7;
        int c = k % 7;
        float s0 = 0.f, s1 = 0.f;
        #pragma unroll 2
        for (int i = 0; i < HDIM; i += 2) {
            s0 += hs[s][i  ][c] * __ldg(&W_out[(i  )*4 + o]);
            s1 += hs[s][i+1][c] * __ldg(&W_out[(i+1)*4 + o]);
        }
        float acc = s0 + s1;
        if (c == 0) acc += b_out[o];
        zsh[s][o][c] = acc;
    }
    __syncthreads();

    // ---------------- residual assembly ----------------
    if (j < SPB) {
        int s = j;
        int n = n0 + s;
        if (n < N) {
            float u   = zsh[s][0][0], ux = zsh[s][0][1], uy = zsh[s][0][2], ut = zsh[s][0][3];
            float uxx = zsh[s][0][4], uyy = zsh[s][0][5];
            float v   = zsh[s][1][0], vx = zsh[s][1][1], vy = zsh[s][1][2], vt = zsh[s][1][3];
            float vxx = zsh[s][1][4], vyy = zsh[s][1][5];
            float pe  = expf(zsh[s][2][0]);
            float p_x = pe * zsh[s][2][1];
            float p_y = pe * zsh[s][2][2];
            float z3  = zsh[s][3][0];
            float aa  = 1.0f / (1.0f + expf(-z3));
            float da  = aa * (1.0f - aa);
            float zax = zsh[s][3][1], zay = zsh[s][3][2], zat = zsh[s][3][3];
            float ax  = da * zax, ay = da * zay, at = da * zat;
            float om  = da * (1.0f - 2.0f*aa);
            float axx = om*zax*zax + da*zsh[s][3][4];
            float ayy = om*zay*zay + da*zsh[s][3][5];
            float axy = om*zax*zay + da*zsh[s][3][6];

            const float MU1 = 1.0f, MU2 = 10.0f;
            const float RHO1 = 100.0f, RHO2 = 1000.0f, RHO_REF = 1000.0f;
            const float ONE_WE = 24.5f / (RHO_REF * 1.0f * 0.5f);   // 0.049
            const float ONE_FR = 0.98f * 0.5f / 1.0f;               // 0.49
            const float RE_DEN = RHO_REF * 1.0f * 0.5f;             // 500
            const float EPSC = 2.2204460492503131e-16f;

            float mu  = MU2 + (MU1 - MU2)*aa;
            float mux = (MU1 - MU2)*ax;
            float muy = (MU1 - MU2)*ay;
            float rho = RHO2 + (RHO1 - RHO2)*aa;
            float g   = sqrtf(ax*ax + ay*ay + EPSC);
            float g3  = g*g*g;
            float curv = -((axx + ayy)/g - (ax*ax*axx + ay*ay*ayy + 2.0f*ax*ay*axy)/g3);
            float oRe  = mu  / RE_DEN;
            float oRex = mux / RE_DEN;
            float oRey = muy / RE_DEN;
            float rr   = rho / RHO_REF;

            float PDE_m = ux + vy;
            float PDE_a = at + u*ax + v*ay;
            float PDE_u = (ut + u*ux + v*uy)*rr + p_x - ONE_WE*curv*ax
                        - oRe*(uxx + uyy) - 2.0f*oRex*ux - oRey*(uy + vx);
            float PDE_v = (vt + u*vx + v*vy)*rr + p_y - ONE_WE*curv*ay
                        - oRe*(vxx + vyy) - rr*ONE_FR - 2.0f*oRey*vy - oRex*(uy + vx);

            out[0*N + n] = PDE_m;
            out[1*N + n] = PDE_u;
            out[2*N + n] = PDE_v;
            out[3*N + n] = PDE_a;
        }
    }
}

extern "C" void kernel_launch(void* const* d_in, const int* in_sizes, int n_in,
                              void* d_out, int out_size)
{
    const float* x     = (const float*)d_in[0];
    const float* y     = (const float*)d_in[1];
    const float* t     = (const float*)d_in[2];
    const float* W_in  = (const float*)d_in[3];
    const float* b_in  = (const float*)d_in[4];
    const float* W_h   = (const float*)d_in[5];
    const float* b_h   = (const float*)d_in[6];
    const float* W_out = (const float*)d_in[7];
    const float* b_out = (const float*)d_in[8];
    const float* act   = (const float*)d_in[9];
    float* out = (float*)d_out;
    int N = in_sizes[0];
    int blocks = (N + SPB - 1) / SPB;
    pinn_kernel<<<blocks, NTHREADS>>>(x, y, t, W_in, b_in, W_h, b_h,
                                      W_out, b_out, act, out, N);
}

// round 4
// speedup vs baseline: 1.7068x; 1.2238x over previous
#include <cuda_runtime.h>
#include <cuda_bf16.h>
#include <math.h>
#include <stdint.h>

#define HU       250
#define KPAD     256
#define SPB      16          // samples per block -> M = 128 rows
#define NTHREADS 256         // 8 warps, warp owns 16 rows
#define NHID     6

// ---- smem layout (relative to 1024-aligned base) ----
#define A0_OFF   0            // A hi: 128 rows x 512B (256 bf16, XOR-swizzled)
#define A1_OFF   65536        // A lo
#define B0_OFF   131072       // B hi quarter: 256 n-rows x 128B (64 k bf16)
#define B1_OFF   163840       // B lo quarter
#define CTRL_OFF 196608
#define MBAR_OFF (CTRL_OFF)
#define BIAS_OFF (CTRL_OFF + 64)          // 256 f32
#define ZSH_OFF  (CTRL_OFF + 64 + 1024)   // 16*4*8 f32
#define SMEM_BYTES (CTRL_OFF + 64 + 1024 + 2048 + 1024)

// pre-split weight images: [term][layer][kquarter][n=256][k=64 swizzled]
__device__ __nv_bfloat16 g_B[2][NHID][4][256][64];

// ---------------- helpers ----------------
__device__ __forceinline__ void mbar_init(uint32_t m, uint32_t cnt) {
    asm volatile("mbarrier.init.shared.b64 [%0], %1;" :: "r"(m), "r"(cnt) : "memory");
}
__device__ __forceinline__ void mbar_expect(uint32_t m, uint32_t bytes) {
    asm volatile("mbarrier.arrive.expect_tx.shared.b64 _, [%0], %1;" :: "r"(m), "r"(bytes) : "memory");
}
__device__ __forceinline__ void mbar_wait(uint32_t m, uint32_t ph) {
    asm volatile(
        "{\n\t.reg .pred P1;\n\t"
        "WAIT_LOOP_%=:\n\t"
        "mbarrier.try_wait.parity.acquire.cta.shared::cta.b64 P1, [%0], %1, 0x989680;\n\t"
        "@P1 bra.uni WAIT_DONE_%=;\n\t"
        "bra.uni WAIT_LOOP_%=;\n\t"
        "WAIT_DONE_%=:\n\t}"
        :: "r"(m), "r"(ph) : "memory");
}
__device__ __forceinline__ void bulk_g2s(uint32_t dst, const void* src, uint32_t bytes, uint32_t mbar) {
    asm volatile("cp.async.bulk.shared::cluster.global.mbarrier::complete_tx::bytes [%0], [%1], %2, [%3];"
                 :: "r"(dst), "l"(src), "r"(bytes), "r"(mbar) : "memory");
}
__device__ __forceinline__ void ldmx4(uint32_t& r0, uint32_t& r1, uint32_t& r2, uint32_t& r3, uint32_t addr) {
    asm volatile("ldmatrix.sync.aligned.m8n8.x4.shared.b16 {%0,%1,%2,%3}, [%4];"
                 : "=r"(r0), "=r"(r1), "=r"(r2), "=r"(r3) : "r"(addr));
}
__device__ __forceinline__ void mma_bf16(float* d, uint32_t a0, uint32_t a1, uint32_t a2, uint32_t a3,
                                         uint32_t b0, uint32_t b1) {
    asm volatile("mma.sync.aligned.m16n8k16.row.col.f32.bf16.bf16.f32 "
                 "{%0,%1,%2,%3}, {%4,%5,%6,%7}, {%8,%9}, {%0,%1,%2,%3};"
                 : "+f"(d[0]), "+f"(d[1]), "+f"(d[2]), "+f"(d[3])
                 : "r"(a0), "r"(a1), "r"(a2), "r"(a3), "r"(b0), "r"(b1));
}
__device__ __forceinline__ uint32_t pack_bf16x2(float lo, float hi) {
    __nv_bfloat16 a = __float2bfloat16(lo);
    __nv_bfloat16 b = __float2bfloat16(hi);
    return ((uint32_t)*(unsigned short*)&b << 16) | (uint32_t)*(unsigned short*)&a;
}
__device__ __forceinline__ float elemh(int ch, float c, float z, float zvb, float zx, float zy) {
    float f  = tanhf(c * zvb);
    float dd = c * (1.0f - f * f);
    float m2 = -2.0f * c * f;
    float t2 = (ch == 4) ? zx * zx : (ch == 5) ? zy * zy : (ch == 6) ? zy * zx : 0.0f;
    float h  = fmaf(m2 * dd, t2, dd * z);
    if (ch == 0) h = f;
    if (ch == 7) h = 0.0f;
    return h;
}

// ---------------- prep: split + transpose + swizzle W_h ----------------
__global__ void prep_kernel(const float* __restrict__ W_h) {
    int idx = blockIdx.x * blockDim.x + threadIdx.x;
    if (idx >= NHID * 4 * 256 * 64) return;
    int kk = idx & 63;
    int n  = (idx >> 6) & 255;
    int kq = (idx >> 14) & 3;
    int l  = idx >> 16;
    int kg = kq * 64 + kk;
    float w = (n < HU && kg < HU) ? W_h[(l * HU + kg) * HU + n] : 0.0f;
    __nv_bfloat16 hi = __float2bfloat16(w);
    __nv_bfloat16 lo = __float2bfloat16(w - __bfloat162float(hi));
    int u  = kk >> 3;
    int up = u ^ (n & 7);
    int off = up * 8 + (kk & 7);
    g_B[0][l][kq][n][off] = hi;
    g_B[1][l][kq][n][off] = lo;
}

// ---------------- main kernel ----------------
__global__ __launch_bounds__(NTHREADS, 1)
void pinn_mma_kernel(const float* __restrict__ x,
                     const float* __restrict__ y,
                     const float* __restrict__ t,
                     const float* __restrict__ W_in,
                     const float* __restrict__ b_in,
                     const float* __restrict__ b_h,
                     const float* __restrict__ W_out,
                     const float* __restrict__ b_out,
                     const float* __restrict__ act,
                     float* __restrict__ out,
                     int N)
{
    extern __shared__ char smraw[];
    char* sm = (char*)(((uintptr_t)smraw + 1023) & ~(uintptr_t)1023);
    uint32_t smb;
    asm("{ .reg .u64 tmp; cvta.to.shared.u64 tmp, %1; cvt.u32.u64 %0, tmp; }"
        : "=r"(smb) : "l"(sm));

    const int tid = threadIdx.x;
    const int wid = tid >> 5;          // 0..7
    const int lid = tid & 31;
    const int n0g = blockIdx.x * SPB;
    float* bias_sm = (float*)(sm + BIAS_OFF);

    if (tid == 0) mbar_init(smb + MBAR_OFF, 1);

    // -------- input layer: fill A0/A1 (bf16 split, swizzled) --------
    {
        const float c0 = 10.0f * __ldg(&act[0]);
        for (int idx = tid; idx < SPB * KPAD; idx += NTHREADS) {
            int s = idx >> 8, n = idx & 255;
            float hv[8] = {0.f, 0.f, 0.f, 0.f, 0.f, 0.f, 0.f, 0.f};
            if (n < HU) {
                int gn = n0g + s;
                float px = 0.f, py = 0.f, pt = 0.f;
                if (gn < N) { px = x[gn]; py = y[gn]; pt = t[gn]; }
                float w0 = __ldg(&W_in[n]);
                float w1 = __ldg(&W_in[HU + n]);
                float w2 = __ldg(&W_in[2 * HU + n]);
                float bj = __ldg(&b_in[n]);
                float z = px * w0 + py * w1 + pt * w2 + bj;
                float f = tanhf(c0 * z);
                float d = c0 * (1.0f - f * f);
                float fx = d * w0, fy = d * w1;
                float m2 = -2.0f * c0 * f;
                hv[0] = f;  hv[1] = fx; hv[2] = fy; hv[3] = d * w2;
                hv[4] = m2 * fx * w0; hv[5] = m2 * fy * w1; hv[6] = m2 * fy * w0;
            }
            #pragma unroll
            for (int c = 0; c < 8; ++c) {
                int row = 8 * s + c;
                uint32_t addr = (uint32_t)(row * 512 + (((n >> 3) ^ (row & 7)) << 4) + (n & 7) * 2);
                float v = hv[c];
                __nv_bfloat16 hi = __float2bfloat16(v);
                *(__nv_bfloat16*)(sm + A0_OFF + addr) = hi;
                *(__nv_bfloat16*)(sm + A1_OFF + addr) = __float2bfloat16(v - __bfloat162float(hi));
            }
        }
    }
    __syncthreads();

    // lane-constant address pieces
    const int arow   = 16 * wid + ((lid >> 3) & 1) * 8 + (lid & 7);
    const int bln    = ((lid >> 3) & 1) * 8 + (lid & 7);   // n within 16-group
    const int khalf  = (lid >> 4);                         // 0 or 1 -> +8 k
    const int l7     = lid & 7;

    uint32_t phase = 0;

    #pragma unroll 1
    for (int l = 0; l < NHID; ++l) {
        bias_sm[tid] = (tid < HU) ? __ldg(&b_h[l * HU + tid]) : 0.0f;

        float d[32][4];
        #pragma unroll
        for (int j = 0; j < 32; ++j) {
            d[j][0] = 0.f; d[j][1] = 0.f; d[j][2] = 0.f; d[j][3] = 0.f;
        }

        #pragma unroll 1
        for (int q = 0; q < 4; ++q) {
            if (tid == 0) {
                mbar_expect(smb + MBAR_OFF, 65536);
                bulk_g2s(smb + B0_OFF, &g_B[0][l][q][0][0], 32768, smb + MBAR_OFF);
                bulk_g2s(smb + B1_OFF, &g_B[1][l][q][0][0], 32768, smb + MBAR_OFF);
            }
            mbar_wait(smb + MBAR_OFF, phase); phase ^= 1;

            #pragma unroll 1
            for (int pass = 0; pass < 3; ++pass) {
                const uint32_t Abase = smb + ((pass == 2) ? A1_OFF : A0_OFF);
                const uint32_t Bbase = smb + ((pass == 1) ? B1_OFF : B0_OFF);
                #pragma unroll 1
                for (int kk4 = 0; kk4 < 4; ++kk4) {
                    int aku = q * 8 + kk4 * 2 + khalf;          // 16B unit of A k
                    uint32_t aaddr = Abase + arow * 512 + (uint32_t)((aku ^ l7) << 4);
                    uint32_t a0, a1, a2, a3;
                    ldmx4(a0, a1, a2, a3, aaddr);

                    int bku = kk4 * 2 + khalf;                  // 16B unit of B k (within quarter)
                    uint32_t bbase_l = Bbase + bln * 128 + (uint32_t)((bku ^ l7) << 4);
                    #pragma unroll
                    for (int j2 = 0; j2 < 16; ++j2) {
                        uint32_t b0, b1, b2, b3;
                        ldmx4(b0, b1, b2, b3, bbase_l + (uint32_t)(j2 * 2048));
                        mma_bf16(d[2 * j2],     a0, a1, a2, a3, b0, b2);
                        mma_bf16(d[2 * j2 + 1], a0, a1, a2, a3, b1, b3);
                    }
                }
            }
            __syncthreads();   // B buffer consumed by all warps; A safe after last q
        }

        // -------- epilogue --------
        const float cl = 10.0f * __ldg(&act[l + 1]);
        const int ch   = lid >> 2;
        const int srcv = lid & 3, srcx = 4 | (lid & 3), srcy = 8 | (lid & 3);
        const int rA = 16 * wid + ch, rB = 16 * wid + 8 + ch;
        const int sA = 2 * wid, sB = 2 * wid + 1;
        float* hsb = (float*)sm;

        #pragma unroll
        for (int j = 0; j < 32; ++j) {
            int n0 = 8 * j + 2 * (lid & 3);
            float bv0 = bias_sm[n0], bv1 = bias_sm[n0 + 1];

            float zv0 = __shfl_sync(0xffffffffu, d[j][0], srcv);
            float zv1 = __shfl_sync(0xffffffffu, d[j][1], srcv);
            float zx0 = __shfl_sync(0xffffffffu, d[j][0], srcx);
            float zx1 = __shfl_sync(0xffffffffu, d[j][1], srcx);
            float zy0 = __shfl_sync(0xffffffffu, d[j][0], srcy);
            float zy1 = __shfl_sync(0xffffffffu, d[j][1], srcy);
            float hA0 = elemh(ch, cl, d[j][0], zv0 + bv0, zx0, zy0);
            float hA1 = elemh(ch, cl, d[j][1], zv1 + bv1, zx1, zy1);

            float wv0 = __shfl_sync(0xffffffffu, d[j][2], srcv);
            float wv1 = __shfl_sync(0xffffffffu, d[j][3], srcv);
            float wx0 = __shfl_sync(0xffffffffu, d[j][2], srcx);
            float wx1 = __shfl_sync(0xffffffffu, d[j][3], srcx);
            float wy0 = __shfl_sync(0xffffffffu, d[j][2], srcy);
            float wy1 = __shfl_sync(0xffffffffu, d[j][3], srcy);
            float hB0 = elemh(ch, cl, d[j][2], wv0 + bv0, wx0, wy0);
            float hB1 = elemh(ch, cl, d[j][3], wv1 + bv1, wx1, wy1);

            if (n0 >= HU)     { hA0 = 0.f; hB0 = 0.f; }
            if (n0 + 1 >= HU) { hA1 = 0.f; hB1 = 0.f; }

            if (l < NHID - 1) {
                uint32_t offA = (uint32_t)(rA * 512 + ((j ^ (rA & 7)) << 4) + (n0 & 7) * 2);
                uint32_t offB = (uint32_t)(rB * 512 + ((j ^ (rB & 7)) << 4) + (n0 & 7) * 2);
                float lA0 = hA0 - __bfloat162float(__float2bfloat16(hA0));
                float lA1 = hA1 - __bfloat162float(__float2bfloat16(hA1));
                float lB0 = hB0 - __bfloat162float(__float2bfloat16(hB0));
                float lB1 = hB1 - __bfloat162float(__float2bfloat16(hB1));
                *(uint32_t*)(sm + A0_OFF + offA) = pack_bf16x2(hA0, hA1);
                *(uint32_t*)(sm + A1_OFF + offA) = pack_bf16x2(lA0, lA1);
                *(uint32_t*)(sm + A0_OFF + offB) = pack_bf16x2(hB0, hB1);
                *(uint32_t*)(sm + A1_OFF + offB) = pack_bf16x2(lB0, lB1);
            } else {
                if (n0 < HU) {
                    hsb[(sA * 256 + n0) * 8 + ch] = hA0;
                    hsb[(sB * 256 + n0) * 8 + ch] = hB0;
                }
                if (n0 + 1 < HU) {
                    hsb[(sA * 256 + n0 + 1) * 8 + ch] = hA1;
                    hsb[(sB * 256 + n0 + 1) * 8 + ch] = hB1;
                }
            }
        }
        __syncthreads();
    }

    // -------- output layer: 16 samples x 4 outs x 7 channels --------
    {
        float* hsb = (float*)sm;
        float* zsh = (float*)(sm + ZSH_OFF);
        for (int idx = tid; idx < SPB * 28; idx += NTHREADS) {
            int s = idx / 28, k2 = idx % 28, o = k2 / 7, c = k2 % 7;
            float acc = (c == 0) ? __ldg(&b_out[o]) : 0.f;
            for (int n = 0; n < HU; ++n)
                acc += hsb[(s * 256 + n) * 8 + c] * __ldg(&W_out[n * 4 + o]);
            zsh[(s * 4 + o) * 8 + c] = acc;
        }
    }
    __syncthreads();

    // -------- residual assembly --------
    if (tid < SPB) {
        int s = tid, n = n0g + s;
        if (n < N) {
            float* zsh = (float*)(sm + ZSH_OFF);
            #define Z(o, c) zsh[((s * 4) + (o)) * 8 + (c)]
            float u = Z(0,0), ux = Z(0,1), uy = Z(0,2), ut = Z(0,3), uxx = Z(0,4), uyy = Z(0,5);
            float v = Z(1,0), vx = Z(1,1), vy = Z(1,2), vt = Z(1,3), vxx = Z(1,4), vyy = Z(1,5);
            float pe  = expf(Z(2,0));
            float p_x = pe * Z(2,1);
            float p_y = pe * Z(2,2);
            float z3  = Z(3,0);
            float aa  = 1.0f / (1.0f + expf(-z3));
            float da  = aa * (1.0f - aa);
            float zax = Z(3,1), zay = Z(3,2), zat = Z(3,3);
            float ax = da * zax, ay = da * zay, at2 = da * zat;
            float om = da * (1.0f - 2.0f * aa);
            float axx = om * zax * zax + da * Z(3,4);
            float ayy = om * zay * zay + da * Z(3,5);
            float axy = om * zax * zay + da * Z(3,6);
            #undef Z
            const float MU1 = 1.0f, MU2 = 10.0f;
            const float RHO1 = 100.0f, RHO2 = 1000.0f, RHO_REF = 1000.0f;
            const float ONE_WE = 24.5f / 500.0f;
            const float ONE_FR = 0.49f;
            const float RE_DEN = 500.0f;
            const float EPSC = 2.2204460492503131e-16f;

            float mu  = MU2 + (MU1 - MU2) * aa;
            float mux = (MU1 - MU2) * ax;
            float muy = (MU1 - MU2) * ay;
            float rho = RHO2 + (RHO1 - RHO2) * aa;
            float g   = sqrtf(ax * ax + ay * ay + EPSC);
            float g3  = g * g * g;
            float curv = -((axx + ayy) / g -
                           (ax * ax * axx + ay * ay * ayy + 2.0f * ax * ay * axy) / g3);
            float oRe  = mu  / RE_DEN;
            float oRex = mux / RE_DEN;
            float oRey = muy / RE_DEN;
            float rr   = rho / RHO_REF;

            float PDE_m = ux + vy;
            float PDE_a = at2 + u * ax + v * ay;
            float PDE_u = (ut + u * ux + v * uy) * rr + p_x - ONE_WE * curv * ax
                        - oRe * (uxx + uyy) - 2.0f * oRex * ux - oRey * (uy + vx);
            float PDE_v = (vt + u * vx + v * vy) * rr + p_y - ONE_WE * curv * ay
                        - oRe * (vxx + vyy) - rr * ONE_FR - 2.0f * oRey * vy - oRex * (uy + vx);

            out[0 * N + n] = PDE_m;
            out[1 * N + n] = PDE_u;
            out[2 * N + n] = PDE_v;
            out[3 * N + n] = PDE_a;
        }
    }
    __syncthreads();
    if (tid == 0)
        asm volatile("mbarrier.inval.shared.b64 [%0];" :: "r"(smb + MBAR_OFF) : "memory");
}

extern "C" void kernel_launch(void* const* d_in, const int* in_sizes, int n_in,
                              void* d_out, int out_size)
{
    const float* x     = (const float*)d_in[0];
    const float* y     = (const float*)d_in[1];
    const float* t     = (const float*)d_in[2];
    const float* W_in  = (const float*)d_in[3];
    const float* b_in  = (const float*)d_in[4];
    const float* W_h   = (const float*)d_in[5];
    const float* b_h   = (const float*)d_in[6];
    const float* W_out = (const float*)d_in[7];
    const float* b_out = (const float*)d_in[8];
    const float* act   = (const float*)d_in[9];
    float* out = (float*)d_out;
    int N = in_sizes[0];

    cudaFuncSetAttribute(pinn_mma_kernel,
                         cudaFuncAttributeMaxDynamicSharedMemorySize, SMEM_BYTES);

    prep_kernel<<<(NHID * 4 * 256 * 64 + 255) / 256, 256>>>(W_h);

    int blocks = (N + SPB - 1) / SPB;
    pinn_mma_kernel<<<blocks, NTHREADS, SMEM_BYTES>>>(
        x, y, t, W_in, b_in, b_h, W_out, b_out, act, out, N);
}

// round 5
// speedup vs baseline: 2.3674x; 1.3871x over previous
#include <cuda_runtime.h>
#include <cuda_bf16.h>
#include <math.h>
#include <stdint.h>

#define HU       250
#define KPAD     256
#define SPB      16          // samples per block -> M = 128 rows
#define NTHREADS 512         // 16 warps: warp = (stripe 0..7, n-half 0..1)
#define NHID     6
#define NCHUNK   8           // k chunks of 32 per layer
#define TOTCH    (NHID*NCHUNK)

// ---- smem layout (relative to 1024-aligned base) ----
#define A0_OFF   0            // A hi: 128 rows x 512B (256 bf16, XOR-swizzled)
#define A1_OFF   65536        // A lo
#define B_OFF    131072       // 2 stages x (hi 16KB + lo 16KB) = 64KB
#define CTRL_OFF 196608
#define MBAR_OFF (CTRL_OFF)            // 2 mbarriers
#define BIAS_OFF (CTRL_OFF + 64)       // 256 f32
#define ZSH_OFF  (CTRL_OFF + 64 + 1024)
#define SMEM_BYTES (CTRL_OFF + 64 + 1024 + 2048 + 1024)

// pre-split weight images: [term][layer][chunk][n=256][k=32 swizzled]
__device__ __nv_bfloat16 g_B[2][NHID][NCHUNK][256][32];

// ---------------- helpers ----------------
__device__ __forceinline__ void mbar_init(uint32_t m, uint32_t cnt) {
    asm volatile("mbarrier.init.shared.b64 [%0], %1;" :: "r"(m), "r"(cnt) : "memory");
}
__device__ __forceinline__ void mbar_expect(uint32_t m, uint32_t bytes) {
    asm volatile("mbarrier.arrive.expect_tx.shared.b64 _, [%0], %1;" :: "r"(m), "r"(bytes) : "memory");
}
__device__ __forceinline__ void mbar_wait(uint32_t m, uint32_t ph) {
    asm volatile(
        "{\n\t.reg .pred P1;\n\t"
        "WAIT_LOOP_%=:\n\t"
        "mbarrier.try_wait.parity.acquire.cta.shared::cta.b64 P1, [%0], %1, 0x989680;\n\t"
        "@P1 bra.uni WAIT_DONE_%=;\n\t"
        "bra.uni WAIT_LOOP_%=;\n\t"
        "WAIT_DONE_%=:\n\t}"
        :: "r"(m), "r"(ph) : "memory");
}
__device__ __forceinline__ void bulk_g2s(uint32_t dst, const void* src, uint32_t bytes, uint32_t mbar) {
    asm volatile("cp.async.bulk.shared::cluster.global.mbarrier::complete_tx::bytes [%0], [%1], %2, [%3];"
                 :: "r"(dst), "l"(src), "r"(bytes), "r"(mbar) : "memory");
}
__device__ __forceinline__ void ldmx4(uint32_t& r0, uint32_t& r1, uint32_t& r2, uint32_t& r3, uint32_t addr) {
    asm volatile("ldmatrix.sync.aligned.m8n8.x4.shared.b16 {%0,%1,%2,%3}, [%4];"
                 : "=r"(r0), "=r"(r1), "=r"(r2), "=r"(r3) : "r"(addr));
}
__device__ __forceinline__ void mma_bf16(float* d, uint32_t a0, uint32_t a1, uint32_t a2, uint32_t a3,
                                         uint32_t b0, uint32_t b1) {
    asm volatile("mma.sync.aligned.m16n8k16.row.col.f32.bf16.bf16.f32 "
                 "{%0,%1,%2,%3}, {%4,%5,%6,%7}, {%8,%9}, {%0,%1,%2,%3};"
                 : "+f"(d[0]), "+f"(d[1]), "+f"(d[2]), "+f"(d[3])
                 : "r"(a0), "r"(a1), "r"(a2), "r"(a3), "r"(b0), "r"(b1));
}
__device__ __forceinline__ uint32_t pack_bf16x2(float lo, float hi) {
    __nv_bfloat16 a = __float2bfloat16(lo);
    __nv_bfloat16 b = __float2bfloat16(hi);
    return ((uint32_t)*(unsigned short*)&b << 16) | (uint32_t)*(unsigned short*)&a;
}
__device__ __forceinline__ float elemh(int ch, float c, float z, float zvb, float zx, float zy) {
    float f  = tanhf(c * zvb);
    float dd = c * (1.0f - f * f);
    float m2 = -2.0f * c * f;
    float t2 = (ch == 4) ? zx * zx : (ch == 5) ? zy * zy : (ch == 6) ? zy * zx : 0.0f;
    float h  = fmaf(m2 * dd, t2, dd * z);
    if (ch == 0) h = f;
    if (ch == 7) h = 0.0f;
    return h;
}

// ---------------- prep: split + transpose + swizzle W_h ----------------
// B row = 32 bf16 = 64B = 4 units of 16B; swizzle unit' = unit ^ ((n>>1)&3)
__global__ void prep_kernel(const float* __restrict__ W_h) {
    int idx = blockIdx.x * blockDim.x + threadIdx.x;
    if (idx >= NHID * NCHUNK * 256 * 32) return;
    int kk = idx & 31;
    int n  = (idx >> 5) & 255;
    int kc = (idx >> 13) & 7;
    int l  = idx >> 16;
    int kg = kc * 32 + kk;
    float w = (n < HU && kg < HU) ? W_h[(l * HU + kg) * HU + n] : 0.0f;
    __nv_bfloat16 hi = __float2bfloat16(w);
    __nv_bfloat16 lo = __float2bfloat16(w - __bfloat162float(hi));
    int u  = kk >> 3;
    int up = u ^ ((n >> 1) & 3);
    int off = up * 8 + (kk & 7);
    g_B[0][l][kc][n][off] = hi;
    g_B[1][l][kc][n][off] = lo;
}

// ---------------- main kernel ----------------
__global__ __launch_bounds__(NTHREADS, 1)
void pinn_mma_kernel(const float* __restrict__ x,
                     const float* __restrict__ y,
                     const float* __restrict__ t,
                     const float* __restrict__ W_in,
                     const float* __restrict__ b_in,
                     const float* __restrict__ b_h,
                     const float* __restrict__ W_out,
                     const float* __restrict__ b_out,
                     const float* __restrict__ act,
                     float* __restrict__ out,
                     int N)
{
    extern __shared__ char smraw[];
    char* sm = (char*)(((uintptr_t)smraw + 1023) & ~(uintptr_t)1023);
    uint32_t smb;
    asm("{ .reg .u64 tmp; cvta.to.shared.u64 tmp, %1; cvt.u32.u64 %0, tmp; }"
        : "=r"(smb) : "l"(sm));

    const int tid = threadIdx.x;
    const int wid = tid >> 5;          // 0..15
    const int lid = tid & 31;
    const int sw  = wid >> 1;          // stripe 0..7 (rows 16*sw..)
    const int nh  = wid & 1;           // n-half
    const int n0g = blockIdx.x * SPB;
    float* bias_sm = (float*)(sm + BIAS_OFF);

    if (tid == 0) { mbar_init(smb + MBAR_OFF, 1); mbar_init(smb + MBAR_OFF + 8, 1); }

    // -------- input layer: fill A0/A1 (bf16 split, swizzled) --------
    {
        const float c0 = 10.0f * __ldg(&act[0]);
        for (int idx = tid; idx < SPB * KPAD; idx += NTHREADS) {
            int s = idx >> 8, n = idx & 255;
            float hv[8] = {0.f, 0.f, 0.f, 0.f, 0.f, 0.f, 0.f, 0.f};
            if (n < HU) {
                int gn = n0g + s;
                float px = 0.f, py = 0.f, pt = 0.f;
                if (gn < N) { px = x[gn]; py = y[gn]; pt = t[gn]; }
                float w0 = __ldg(&W_in[n]);
                float w1 = __ldg(&W_in[HU + n]);
                float w2 = __ldg(&W_in[2 * HU + n]);
                float bj = __ldg(&b_in[n]);
                float z = px * w0 + py * w1 + pt * w2 + bj;
                float f = tanhf(c0 * z);
                float d = c0 * (1.0f - f * f);
                float fx = d * w0, fy = d * w1;
                float m2 = -2.0f * c0 * f;
                hv[0] = f;  hv[1] = fx; hv[2] = fy; hv[3] = d * w2;
                hv[4] = m2 * fx * w0; hv[5] = m2 * fy * w1; hv[6] = m2 * fy * w0;
            }
            #pragma unroll
            for (int c = 0; c < 8; ++c) {
                int row = 8 * s + c;
                uint32_t addr = (uint32_t)(row * 512 + (((n >> 3) ^ (row & 7)) << 4) + (n & 7) * 2);
                float v = hv[c];
                __nv_bfloat16 hi = __float2bfloat16(v);
                *(__nv_bfloat16*)(sm + A0_OFF + addr) = hi;
                *(__nv_bfloat16*)(sm + A1_OFF + addr) = __float2bfloat16(v - __bfloat162float(hi));
            }
        }
    }
    __syncthreads();

    // prologue TMA: chunks 0,1 into stages 0,1
    if (tid == 0) {
        #pragma unroll
        for (int st = 0; st < 2; ++st) {
            uint32_t dst = smb + B_OFF + st * 32768;
            mbar_expect(smb + MBAR_OFF + st * 8, 32768);
            bulk_g2s(dst,          &g_B[0][0][st][0][0], 16384, smb + MBAR_OFF + st * 8);
            bulk_g2s(dst + 16384,  &g_B[1][0][st][0][0], 16384, smb + MBAR_OFF + st * 8);
        }
    }

    // lane-constant address pieces
    const int arow = 16 * sw + ((lid >> 3) & 1) * 8 + (lid & 7);
    const int bln  = ((lid >> 3) & 1) * 8 + (lid & 7);     // n within 16-group
    const int khalf = (lid >> 4);
    const int l7    = lid & 7;
    const uint32_t bswz = (uint32_t)((bln >> 1) & 3);

    uint32_t ph0 = 0, ph1 = 0;

    #pragma unroll 1
    for (int l = 0; l < NHID; ++l) {
        if (tid < 256) bias_sm[tid] = (tid < HU) ? __ldg(&b_h[l * HU + tid]) : 0.0f;

        float d[16][4];
        #pragma unroll
        for (int j = 0; j < 16; ++j) {
            d[j][0] = 0.f; d[j][1] = 0.f; d[j][2] = 0.f; d[j][3] = 0.f;
        }

        #pragma unroll 1
        for (int c = 0; c < NCHUNK; ++c) {
            const int ci = l * NCHUNK + c;
            const int st = ci & 1;
            const uint32_t mb = smb + MBAR_OFF + st * 8;
            if (st == 0) { mbar_wait(mb, ph0); ph0 ^= 1; }
            else         { mbar_wait(mb, ph1); ph1 ^= 1; }

            const uint32_t Bst = smb + B_OFF + st * 32768;
            #pragma unroll
            for (int ks = 0; ks < 2; ++ks) {
                int aku = c * 4 + ks * 2 + khalf;
                uint32_t aaddr = smb + A0_OFF + arow * 512 + (uint32_t)((aku ^ l7) << 4);
                uint32_t a0, a1, a2, a3, e0, e1, e2, e3;
                ldmx4(a0, a1, a2, a3, aaddr);
                ldmx4(e0, e1, e2, e3, aaddr + (A1_OFF - A0_OFF));

                uint32_t u = (uint32_t)(ks * 2 + khalf);
                uint32_t blane = Bst + (uint32_t)((nh * 128 + bln) * 64) + ((u ^ bswz) << 4);
                #pragma unroll
                for (int j2 = 0; j2 < 8; ++j2) {
                    uint32_t b0, b1, b2, b3;
                    ldmx4(b0, b1, b2, b3, blane + (uint32_t)(j2 * 1024));
                    mma_bf16(d[2 * j2],     a0, a1, a2, a3, b0, b2);
                    mma_bf16(d[2 * j2 + 1], a0, a1, a2, a3, b1, b3);
                    mma_bf16(d[2 * j2],     e0, e1, e2, e3, b0, b2);   // A1*B0
                    mma_bf16(d[2 * j2 + 1], e0, e1, e2, e3, b1, b3);
                    uint32_t c0, c1, c2, c3;
                    ldmx4(c0, c1, c2, c3, blane + 16384u + (uint32_t)(j2 * 1024));
                    mma_bf16(d[2 * j2],     a0, a1, a2, a3, c0, c2);   // A0*B1
                    mma_bf16(d[2 * j2 + 1], a0, a1, a2, a3, c1, c3);
                }
            }
            __syncthreads();     // stage drained by all warps
            if (tid == 0 && ci + 2 < TOTCH) {
                int ci2 = ci + 2;
                int l2 = ci2 >> 3, c2 = ci2 & 7;
                uint32_t dst = smb + B_OFF + st * 32768;
                mbar_expect(mb, 32768);
                bulk_g2s(dst,         &g_B[0][l2][c2][0][0], 16384, mb);
                bulk_g2s(dst + 16384, &g_B[1][l2][c2][0][0], 16384, mb);
            }
        }

        // -------- epilogue --------
        const float cl = 10.0f * __ldg(&act[l + 1]);
        const int ch   = lid >> 2;
        const int srcv = lid & 3, srcx = 4 | (lid & 3), srcy = 8 | (lid & 3);
        const int rA = 16 * sw + ch, rB = 16 * sw + 8 + ch;
        const int sA = 2 * sw, sB = 2 * sw + 1;
        float* hsb = (float*)sm;

        #pragma unroll
        for (int j = 0; j < 16; ++j) {
            int n0 = nh * 128 + 8 * j + 2 * (lid & 3);
            float bv0 = bias_sm[n0], bv1 = bias_sm[n0 + 1];

            float zv0 = __shfl_sync(0xffffffffu, d[j][0], srcv);
            float zv1 = __shfl_sync(0xffffffffu, d[j][1], srcv);
            float zx0 = __shfl_sync(0xffffffffu, d[j][0], srcx);
            float zx1 = __shfl_sync(0xffffffffu, d[j][1], srcx);
            float zy0 = __shfl_sync(0xffffffffu, d[j][0], srcy);
            float zy1 = __shfl_sync(0xffffffffu, d[j][1], srcy);
            float hA0 = elemh(ch, cl, d[j][0], zv0 + bv0, zx0, zy0);
            float hA1 = elemh(ch, cl, d[j][1], zv1 + bv1, zx1, zy1);

            float wv0 = __shfl_sync(0xffffffffu, d[j][2], srcv);
            float wv1 = __shfl_sync(0xffffffffu, d[j][3], srcv);
            float wx0 = __shfl_sync(0xffffffffu, d[j][2], srcx);
            float wx1 = __shfl_sync(0xffffffffu, d[j][3], srcx);
            float wy0 = __shfl_sync(0xffffffffu, d[j][2], srcy);
            float wy1 = __shfl_sync(0xffffffffu, d[j][3], srcy);
            float hB0 = elemh(ch, cl, d[j][2], wv0 + bv0, wx0, wy0);
            float hB1 = elemh(ch, cl, d[j][3], wv1 + bv1, wx1, wy1);

            if (n0 >= HU)     { hA0 = 0.f; hB0 = 0.f; }
            if (n0 + 1 >= HU) { hA1 = 0.f; hB1 = 0.f; }

            int unit = nh * 16 + j;
            if (l < NHID - 1) {
                uint32_t offA = (uint32_t)(rA * 512 + ((unit ^ (rA & 7)) << 4) + (n0 & 7) * 2);
                uint32_t offB = (uint32_t)(rB * 512 + ((unit ^ (rB & 7)) << 4) + (n0 & 7) * 2);
                float lA0 = hA0 - __bfloat162float(__float2bfloat16(hA0));
                float lA1 = hA1 - __bfloat162float(__float2bfloat16(hA1));
                float lB0 = hB0 - __bfloat162float(__float2bfloat16(hB0));
                float lB1 = hB1 - __bfloat162float(__float2bfloat16(hB1));
                *(uint32_t*)(sm + A0_OFF + offA) = pack_bf16x2(hA0, hA1);
                *(uint32_t*)(sm + A1_OFF + offA) = pack_bf16x2(lA0, lA1);
                *(uint32_t*)(sm + A0_OFF + offB) = pack_bf16x2(hB0, hB1);
                *(uint32_t*)(sm + A1_OFF + offB) = pack_bf16x2(lB0, lB1);
            } else {
                if (n0 < HU) {
                    hsb[(sA * 256 + n0) * 8 + ch] = hA0;
                    hsb[(sB * 256 + n0) * 8 + ch] = hB0;
                }
                if (n0 + 1 < HU) {
                    hsb[(sA * 256 + n0 + 1) * 8 + ch] = hA1;
                    hsb[(sB * 256 + n0 + 1) * 8 + ch] = hB1;
                }
            }
        }
        __syncthreads();
    }

    // -------- output layer: 16 samples x 4 outs x 7 channels --------
    {
        float* hsb = (float*)sm;
        float* zsh = (float*)(sm + ZSH_OFF);
        for (int idx = tid; idx < SPB * 28; idx += NTHREADS) {
            int s = idx / 28, k2 = idx % 28, o = k2 / 7, c = k2 % 7;
            float acc = (c == 0) ? __ldg(&b_out[o]) : 0.f;
            for (int n = 0; n < HU; ++n)
                acc += hsb[(s * 256 + n) * 8 + c] * __ldg(&W_out[n * 4 + o]);
            zsh[(s * 4 + o) * 8 + c] = acc;
        }
    }
    __syncthreads();

    // -------- residual assembly --------
    if (tid < SPB) {
        int s = tid, n = n0g + s;
        if (n < N) {
            float* zsh = (float*)(sm + ZSH_OFF);
            #define Z(o, c) zsh[((s * 4) + (o)) * 8 + (c)]
            float u = Z(0,0), ux = Z(0,1), uy = Z(0,2), ut = Z(0,3), uxx = Z(0,4), uyy = Z(0,5);
            float v = Z(1,0), vx = Z(1,1), vy = Z(1,2), vt = Z(1,3), vxx = Z(1,4), vyy = Z(1,5);
            float pe  = expf(Z(2,0));
            float p_x = pe * Z(2,1);
            float p_y = pe * Z(2,2);
            float z3  = Z(3,0);
            float aa  = 1.0f / (1.0f + expf(-z3));
            float da  = aa * (1.0f - aa);
            float zax = Z(3,1), zay = Z(3,2), zat = Z(3,3);
            float ax = da * zax, ay = da * zay, at2 = da * zat;
            float om = da * (1.0f - 2.0f * aa);
            float axx = om * zax * zax + da * Z(3,4);
            float ayy = om * zay * zay + da * Z(3,5);
            float axy = om * zax * zay + da * Z(3,6);
            #undef Z
            const float MU1 = 1.0f, MU2 = 10.0f;
            const float RHO1 = 100.0f, RHO2 = 1000.0f, RHO_REF = 1000.0f;
            const float ONE_WE = 24.5f / 500.0f;
            const float ONE_FR = 0.49f;
            const float RE_DEN = 500.0f;
            const float EPSC = 2.2204460492503131e-16f;

            float mu  = MU2 + (MU1 - MU2) * aa;
            float mux = (MU1 - MU2) * ax;
            float muy = (MU1 - MU2) * ay;
            float rho = RHO2 + (RHO1 - RHO2) * aa;
            float g   = sqrtf(ax * ax + ay * ay + EPSC);
            float g3  = g * g * g;
            float curv = -((axx + ayy) / g -
                           (ax * ax * axx + ay * ay * ayy + 2.0f * ax * ay * axy) / g3);
            float oRe  = mu  / RE_DEN;
            float oRex = mux / RE_DEN;
            float oRey = muy / RE_DEN;
            float rr   = rho / RHO_REF;

            float PDE_m = ux + vy;
            float PDE_a = at2 + u * ax + v * ay;
            float PDE_u = (ut + u * ux + v * uy) * rr + p_x - ONE_WE * curv * ax
                        - oRe * (uxx + uyy) - 2.0f * oRex * ux - oRey * (uy + vx);
            float PDE_v = (vt + u * vx + v * vy) * rr + p_y - ONE_WE * curv * ay
                        - oRe * (vxx + vyy) - rr * ONE_FR - 2.0f * oRey * vy - oRex * (uy + vx);

            out[0 * N + n] = PDE_m;
            out[1 * N + n] = PDE_u;
            out[2 * N + n] = PDE_v;
            out[3 * N + n] = PDE_a;
        }
    }
    __syncthreads();
    if (tid == 0) {
        asm volatile("mbarrier.inval.shared.b64 [%0];" :: "r"(smb + MBAR_OFF) : "memory");
        asm volatile("mbarrier.inval.shared.b64 [%0];" :: "r"(smb + MBAR_OFF + 8) : "memory");
    }
}

extern "C" void kernel_launch(void* const* d_in, const int* in_sizes, int n_in,
                              void* d_out, int out_size)
{
    const float* x     = (const float*)d_in[0];
    const float* y     = (const float*)d_in[1];
    const float* t     = (const float*)d_in[2];
    const float* W_in  = (const float*)d_in[3];
    const float* b_in  = (const float*)d_in[4];
    const float* W_h   = (const float*)d_in[5];
    const float* b_h   = (const float*)d_in[6];
    const float* W_out = (const float*)d_in[7];
    const float* b_out = (const float*)d_in[8];
    const float* act   = (const float*)d_in[9];
    float* out = (float*)d_out;
    int N = in_sizes[0];

    cudaFuncSetAttribute(pinn_mma_kernel,
                         cudaFuncAttributeMaxDynamicSharedMemorySize, SMEM_BYTES);

    prep_kernel<<<(NHID * NCHUNK * 256 * 32 + 255) / 256, 256>>>(W_h);

    int blocks = (N + SPB - 1) / SPB;
    pinn_mma_kernel<<<blocks, NTHREADS, SMEM_BYTES>>>(
        x, y, t, W_in, b_in, b_h, W_out, b_out, act, out, N);
}

// round 6
// speedup vs baseline: 2.4897x; 1.0517x over previous
#include <cuda_runtime.h>
#include <cuda_bf16.h>
#include <math.h>
#include <stdint.h>

#define HU       250
#define KPAD     256
#define SPB      16          // samples per block -> M = 128 rows
#define NTHREADS 512         // 16 warps: warp = (stripe 0..7, n-half 0..1)
#define NHID     6
#define NCHUNK   8           // k chunks of 32 per layer
#define TOTCH    (NHID*NCHUNK)

// ---- smem layout (relative to 1024-aligned base) ----
#define A0_OFF   0            // A hi: 128 rows x 512B (256 bf16, XOR-swizzled)
#define A1_OFF   65536        // A lo
#define B_OFF    131072       // 2 stages x (hi 16KB + lo 16KB) = 64KB
#define CTRL_OFF 196608
#define MBAR_OFF (CTRL_OFF)            // full[2] at +0,+8 ; empty[2] at +16,+24
#define ZSH_OFF  (CTRL_OFF + 64)
#define SMEM_BYTES (CTRL_OFF + 64 + 2048 + 1024)

// pre-split weight images: [term][layer][chunk][n=256][k=32 swizzled]
__device__ __nv_bfloat16 g_B[2][NHID][NCHUNK][256][32];

// ---------------- helpers ----------------
__device__ __forceinline__ void mbar_init(uint32_t m, uint32_t cnt) {
    asm volatile("mbarrier.init.shared.b64 [%0], %1;" :: "r"(m), "r"(cnt) : "memory");
}
__device__ __forceinline__ void mbar_expect(uint32_t m, uint32_t bytes) {
    asm volatile("mbarrier.arrive.expect_tx.shared.b64 _, [%0], %1;" :: "r"(m), "r"(bytes) : "memory");
}
__device__ __forceinline__ void mbar_arrive(uint32_t m) {
    asm volatile("mbarrier.arrive.shared.b64 _, [%0];" :: "r"(m) : "memory");
}
__device__ __forceinline__ void mbar_wait(uint32_t m, uint32_t ph) {
    asm volatile(
        "{\n\t.reg .pred P1;\n\t"
        "WAIT_LOOP_%=:\n\t"
        "mbarrier.try_wait.parity.acquire.cta.shared::cta.b64 P1, [%0], %1, 0x989680;\n\t"
        "@P1 bra.uni WAIT_DONE_%=;\n\t"
        "bra.uni WAIT_LOOP_%=;\n\t"
        "WAIT_DONE_%=:\n\t}"
        :: "r"(m), "r"(ph) : "memory");
}
__device__ __forceinline__ void bulk_g2s(uint32_t dst, const void* src, uint32_t bytes, uint32_t mbar) {
    asm volatile("cp.async.bulk.shared::cluster.global.mbarrier::complete_tx::bytes [%0], [%1], %2, [%3];"
                 :: "r"(dst), "l"(src), "r"(bytes), "r"(mbar) : "memory");
}
__device__ __forceinline__ void bar_pair(int id) {
    asm volatile("bar.sync %0, 64;" :: "r"(id) : "memory");
}
__device__ __forceinline__ void ldmx4(uint32_t& r0, uint32_t& r1, uint32_t& r2, uint32_t& r3, uint32_t addr) {
    asm volatile("ldmatrix.sync.aligned.m8n8.x4.shared.b16 {%0,%1,%2,%3}, [%4];"
                 : "=r"(r0), "=r"(r1), "=r"(r2), "=r"(r3) : "r"(addr));
}
__device__ __forceinline__ void mma_bf16(float* d, uint32_t a0, uint32_t a1, uint32_t a2, uint32_t a3,
                                         uint32_t b0, uint32_t b1) {
    asm volatile("mma.sync.aligned.m16n8k16.row.col.f32.bf16.bf16.f32 "
                 "{%0,%1,%2,%3}, {%4,%5,%6,%7}, {%8,%9}, {%0,%1,%2,%3};"
                 : "+f"(d[0]), "+f"(d[1]), "+f"(d[2]), "+f"(d[3])
                 : "r"(a0), "r"(a1), "r"(a2), "r"(a3), "r"(b0), "r"(b1));
}
__device__ __forceinline__ uint32_t pack_bf16x2(float lo, float hi) {
    __nv_bfloat16 a = __float2bfloat16(lo);
    __nv_bfloat16 b = __float2bfloat16(hi);
    return ((uint32_t)*(unsigned short*)&b << 16) | (uint32_t)*(unsigned short*)&a;
}
__device__ __forceinline__ float elemh(int ch, float c, float z, float zvb, float zx, float zy) {
    float f  = tanhf(c * zvb);
    float dd = c * (1.0f - f * f);
    float m2 = -2.0f * c * f;
    float t2 = (ch == 4) ? zx * zx : (ch == 5) ? zy * zy : (ch == 6) ? zy * zx : 0.0f;
    float h  = fmaf(m2 * dd, t2, dd * z);
    if (ch == 0) h = f;
    if (ch == 7) h = 0.0f;
    return h;
}

// ---------------- prep: split + transpose + swizzle W_h ----------------
__global__ void prep_kernel(const float* __restrict__ W_h) {
    int idx = blockIdx.x * blockDim.x + threadIdx.x;
    if (idx >= NHID * NCHUNK * 256 * 32) return;
    int kk = idx & 31;
    int n  = (idx >> 5) & 255;
    int kc = (idx >> 13) & 7;
    int l  = idx >> 16;
    int kg = kc * 32 + kk;
    float w = (n < HU && kg < HU) ? W_h[(l * HU + kg) * HU + n] : 0.0f;
    __nv_bfloat16 hi = __float2bfloat16(w);
    __nv_bfloat16 lo = __float2bfloat16(w - __bfloat162float(hi));
    int u  = kk >> 3;
    int up = u ^ ((n >> 1) & 3);
    int off = up * 8 + (kk & 7);
    g_B[0][l][kc][n][off] = hi;
    g_B[1][l][kc][n][off] = lo;
}

// ---------------- main kernel ----------------
__global__ __launch_bounds__(NTHREADS, 1)
void pinn_mma_kernel(const float* __restrict__ x,
                     const float* __restrict__ y,
                     const float* __restrict__ t,
                     const float* __restrict__ W_in,
                     const float* __restrict__ b_in,
                     const float* __restrict__ b_h,
                     const float* __restrict__ W_out,
                     const float* __restrict__ b_out,
                     const float* __restrict__ act,
                     float* __restrict__ out,
                     int N)
{
    extern __shared__ char smraw[];
    char* sm = (char*)(((uintptr_t)smraw + 1023) & ~(uintptr_t)1023);
    uint32_t smb;
    asm("{ .reg .u64 tmp; cvta.to.shared.u64 tmp, %1; cvt.u32.u64 %0, tmp; }"
        : "=r"(smb) : "l"(sm));

    const int tid = threadIdx.x;
    const int wid = tid >> 5;          // 0..15
    const int lid = tid & 31;
    const int sw  = wid >> 1;          // stripe 0..7
    const int nh  = wid & 1;           // n-half
    const int n0g = blockIdx.x * SPB;

    if (tid == 0) {
        mbar_init(smb + MBAR_OFF + 0,  1);   // full st0
        mbar_init(smb + MBAR_OFF + 8,  1);   // full st1
        mbar_init(smb + MBAR_OFF + 16, 16);  // empty st0
        mbar_init(smb + MBAR_OFF + 24, 16);  // empty st1
    }

    // -------- input layer: fill A0/A1 (bf16 split, swizzled) --------
    {
        const float c0 = 10.0f * __ldg(&act[0]);
        for (int idx = tid; idx < SPB * KPAD; idx += NTHREADS) {
            int s = idx >> 8, n = idx & 255;
            float hv[8] = {0.f, 0.f, 0.f, 0.f, 0.f, 0.f, 0.f, 0.f};
            if (n < HU) {
                int gn = n0g + s;
                float px = 0.f, py = 0.f, pt = 0.f;
                if (gn < N) { px = x[gn]; py = y[gn]; pt = t[gn]; }
                float w0 = __ldg(&W_in[n]);
                float w1 = __ldg(&W_in[HU + n]);
                float w2 = __ldg(&W_in[2 * HU + n]);
                float bj = __ldg(&b_in[n]);
                float z = px * w0 + py * w1 + pt * w2 + bj;
                float f = tanhf(c0 * z);
                float d = c0 * (1.0f - f * f);
                float fx = d * w0, fy = d * w1;
                float m2 = -2.0f * c0 * f;
                hv[0] = f;  hv[1] = fx; hv[2] = fy; hv[3] = d * w2;
                hv[4] = m2 * fx * w0; hv[5] = m2 * fy * w1; hv[6] = m2 * fy * w0;
            }
            #pragma unroll
            for (int c = 0; c < 8; ++c) {
                int row = 8 * s + c;
                uint32_t addr = (uint32_t)(row * 512 + (((n >> 3) ^ (row & 7)) << 4) + (n & 7) * 2);
                float v = hv[c];
                __nv_bfloat16 hi = __float2bfloat16(v);
                *(__nv_bfloat16*)(sm + A0_OFF + addr) = hi;
                *(__nv_bfloat16*)(sm + A1_OFF + addr) = __float2bfloat16(v - __bfloat162float(hi));
            }
        }
    }
    __syncthreads();

    // prologue: fill both stages (no empty-wait needed on first fills)
    if (tid == 0) {
        #pragma unroll
        for (int st = 0; st < 2; ++st) {
            uint32_t dst = smb + B_OFF + st * 32768;
            mbar_expect(smb + MBAR_OFF + st * 8, 32768);
            bulk_g2s(dst,         &g_B[0][0][st][0][0], 16384, smb + MBAR_OFF + st * 8);
            bulk_g2s(dst + 16384, &g_B[1][0][st][0][0], 16384, smb + MBAR_OFF + st * 8);
        }
    }

    // lane-constant address pieces
    const int arow = 16 * sw + ((lid >> 3) & 1) * 8 + (lid & 7);
    const int bln  = ((lid >> 3) & 1) * 8 + (lid & 7);
    const int khalf = (lid >> 4);
    const int l7    = lid & 7;
    const uint32_t bswz = (uint32_t)((bln >> 1) & 3);

    uint32_t ph0 = 0, ph1 = 0;       // consumer full phases
    uint32_t phe0 = 0, phe1 = 0;     // producer empty phases (tid 0 only)

    #pragma unroll 1
    for (int l = 0; l < NHID; ++l) {
        float d[16][4];
        #pragma unroll
        for (int j = 0; j < 16; ++j) {
            d[j][0] = 0.f; d[j][1] = 0.f; d[j][2] = 0.f; d[j][3] = 0.f;
        }

        #pragma unroll 1
        for (int c = 0; c < NCHUNK; ++c) {
            const int ci = l * NCHUNK + c;
            const int st = ci & 1;
            const uint32_t mb_full  = smb + MBAR_OFF + st * 8;
            const uint32_t mb_empty = smb + MBAR_OFF + 16 + st * 8;
            if (st == 0) { mbar_wait(mb_full, ph0); ph0 ^= 1; }
            else         { mbar_wait(mb_full, ph1); ph1 ^= 1; }

            const uint32_t Bst = smb + B_OFF + st * 32768;
            #pragma unroll
            for (int ks = 0; ks < 2; ++ks) {
                int aku = c * 4 + ks * 2 + khalf;
                uint32_t aaddr = smb + A0_OFF + arow * 512 + (uint32_t)((aku ^ l7) << 4);
                uint32_t a0, a1, a2, a3, e0, e1, e2, e3;
                ldmx4(a0, a1, a2, a3, aaddr);
                ldmx4(e0, e1, e2, e3, aaddr + (A1_OFF - A0_OFF));

                uint32_t u = (uint32_t)(ks * 2 + khalf);
                uint32_t blane = Bst + (uint32_t)((nh * 128 + bln) * 64) + ((u ^ bswz) << 4);
                #pragma unroll
                for (int j2 = 0; j2 < 8; ++j2) {
                    uint32_t b0, b1, b2, b3;
                    ldmx4(b0, b1, b2, b3, blane + (uint32_t)(j2 * 1024));
                    mma_bf16(d[2 * j2],     a0, a1, a2, a3, b0, b2);
                    mma_bf16(d[2 * j2 + 1], a0, a1, a2, a3, b1, b3);
                    mma_bf16(d[2 * j2],     e0, e1, e2, e3, b0, b2);   // A1*B0
                    mma_bf16(d[2 * j2 + 1], e0, e1, e2, e3, b1, b3);
                    uint32_t c0, c1, c2, c3;
                    ldmx4(c0, c1, c2, c3, blane + 16384u + (uint32_t)(j2 * 1024));
                    mma_bf16(d[2 * j2],     a0, a1, a2, a3, c0, c2);   // A0*B1
                    mma_bf16(d[2 * j2 + 1], a0, a1, a2, a3, c1, c3);
                }
            }
            // this warp is done with the stage
            if (lid == 0) mbar_arrive(mb_empty);
            // producer: refill this stage with chunk ci+2 once all 16 warps arrived
            if (tid == 0 && ci + 2 < TOTCH) {
                if (st == 0) { mbar_wait(mb_empty, phe0); phe0 ^= 1; }
                else         { mbar_wait(mb_empty, phe1); phe1 ^= 1; }
                int ci2 = ci + 2;
                int l2 = ci2 >> 3, c2 = ci2 & 7;
                uint32_t dst = smb + B_OFF + st * 32768;
                mbar_expect(mb_full, 32768);
                bulk_g2s(dst,         &g_B[0][l2][c2][0][0], 16384, mb_full);
                bulk_g2s(dst + 16384, &g_B[1][l2][c2][0][0], 16384, mb_full);
            }
        }

        // -------- epilogue --------
        // pair-sync: both warps of this stripe are done READING stripe rows of A.
        // last layer: hsb overlay spans other stripes' A -> need full barrier.
        if (l == NHID - 1) __syncthreads();
        else               bar_pair(1 + sw);

        const float cl = 10.0f * __ldg(&act[l + 1]);
        const int ch   = lid >> 2;
        const int srcv = lid & 3, srcx = 4 | (lid & 3), srcy = 8 | (lid & 3);
        const int rA = 16 * sw + ch, rB = 16 * sw + 8 + ch;
        const int sA = 2 * sw, sB = 2 * sw + 1;
        float* hsb = (float*)sm;

        #pragma unroll
        for (int j = 0; j < 16; ++j) {
            int n0 = nh * 128 + 8 * j + 2 * (lid & 3);
            float bv0 = 0.f, bv1 = 0.f;
            if (n0 < HU) {
                float2 bb = *(const float2*)&b_h[l * HU + n0];
                bv0 = bb.x; bv1 = bb.y;
            }

            float zv0 = __shfl_sync(0xffffffffu, d[j][0], srcv);
            float zv1 = __shfl_sync(0xffffffffu, d[j][1], srcv);
            float zx0 = __shfl_sync(0xffffffffu, d[j][0], srcx);
            float zx1 = __shfl_sync(0xffffffffu, d[j][1], srcx);
            float zy0 = __shfl_sync(0xffffffffu, d[j][0], srcy);
            float zy1 = __shfl_sync(0xffffffffu, d[j][1], srcy);
            float hA0 = elemh(ch, cl, d[j][0], zv0 + bv0, zx0, zy0);
            float hA1 = elemh(ch, cl, d[j][1], zv1 + bv1, zx1, zy1);

            float wv0 = __shfl_sync(0xffffffffu, d[j][2], srcv);
            float wv1 = __shfl_sync(0xffffffffu, d[j][3], srcv);
            float wx0 = __shfl_sync(0xffffffffu, d[j][2], srcx);
            float wx1 = __shfl_sync(0xffffffffu, d[j][3], srcx);
            float wy0 = __shfl_sync(0xffffffffu, d[j][2], srcy);
            float wy1 = __shfl_sync(0xffffffffu, d[j][3], srcy);
            float hB0 = elemh(ch, cl, d[j][2], wv0 + bv0, wx0, wy0);
            float hB1 = elemh(ch, cl, d[j][3], wv1 + bv1, wx1, wy1);

            if (n0 >= HU)     { hA0 = 0.f; hB0 = 0.f; }
            if (n0 + 1 >= HU) { hA1 = 0.f; hB1 = 0.f; }

            int unit = nh * 16 + j;
            if (l < NHID - 1) {
                uint32_t offA = (uint32_t)(rA * 512 + ((unit ^ (rA & 7)) << 4) + (n0 & 7) * 2);
                uint32_t offB = (uint32_t)(rB * 512 + ((unit ^ (rB & 7)) << 4) + (n0 & 7) * 2);
                float lA0 = hA0 - __bfloat162float(__float2bfloat16(hA0));
                float lA1 = hA1 - __bfloat162float(__float2bfloat16(hA1));
                float lB0 = hB0 - __bfloat162float(__float2bfloat16(hB0));
                float lB1 = hB1 - __bfloat162float(__float2bfloat16(hB1));
                *(uint32_t*)(sm + A0_OFF + offA) = pack_bf16x2(hA0, hA1);
                *(uint32_t*)(sm + A1_OFF + offA) = pack_bf16x2(lA0, lA1);
                *(uint32_t*)(sm + A0_OFF + offB) = pack_bf16x2(hB0, hB1);
                *(uint32_t*)(sm + A1_OFF + offB) = pack_bf16x2(lB0, lB1);
            } else {
                if (n0 < HU) {
                    hsb[(sA * 256 + n0) * 8 + ch] = hA0;
                    hsb[(sB * 256 + n0) * 8 + ch] = hB0;
                }
                if (n0 + 1 < HU) {
                    hsb[(sA * 256 + n0 + 1) * 8 + ch] = hA1;
                    hsb[(sB * 256 + n0 + 1) * 8 + ch] = hB1;
                }
            }
        }
        // writes visible to pair before its next-layer reads
        if (l < NHID - 1) bar_pair(1 + sw);
    }
    __syncthreads();   // hsb complete

    // -------- output layer: 16 samples x 4 outs x 7 channels --------
    {
        float* hsb = (float*)sm;
        float* zsh = (float*)(sm + ZSH_OFF);
        for (int idx = tid; idx < SPB * 28; idx += NTHREADS) {
            int s = idx / 28, k2 = idx % 28, o = k2 / 7, c = k2 % 7;
            float acc = (c == 0) ? __ldg(&b_out[o]) : 0.f;
            for (int n = 0; n < HU; ++n)
                acc += hsb[(s * 256 + n) * 8 + c] * __ldg(&W_out[n * 4 + o]);
            zsh[(s * 4 + o) * 8 + c] = acc;
        }
    }
    __syncthreads();

    // -------- residual assembly --------
    if (tid < SPB) {
        int s = tid, n = n0g + s;
        if (n < N) {
            float* zsh = (float*)(sm + ZSH_OFF);
            #define Z(o, c) zsh[((s * 4) + (o)) * 8 + (c)]
            float u = Z(0,0), ux = Z(0,1), uy = Z(0,2), ut = Z(0,3), uxx = Z(0,4), uyy = Z(0,5);
            float v = Z(1,0), vx = Z(1,1), vy = Z(1,2), vt = Z(1,3), vxx = Z(1,4), vyy = Z(1,5);
            float pe  = expf(Z(2,0));
            float p_x = pe * Z(2,1);
            float p_y = pe * Z(2,2);
            float z3  = Z(3,0);
            float aa  = 1.0f / (1.0f + expf(-z3));
            float da  = aa * (1.0f - aa);
            float zax = Z(3,1), zay = Z(3,2), zat = Z(3,3);
            float ax = da * zax, ay = da * zay, at2 = da * zat;
            float om = da * (1.0f - 2.0f * aa);
            float axx = om * zax * zax + da * Z(3,4);
            float ayy = om * zay * zay + da * Z(3,5);
            float axy = om * zax * zay + da * Z(3,6);
            #undef Z
            const float MU1 = 1.0f, MU2 = 10.0f;
            const float RHO1 = 100.0f, RHO2 = 1000.0f, RHO_REF = 1000.0f;
            const float ONE_WE = 24.5f / 500.0f;
            const float ONE_FR = 0.49f;
            const float RE_DEN = 500.0f;
            const float EPSC = 2.2204460492503131e-16f;

            float mu  = MU2 + (MU1 - MU2) * aa;
            float mux = (MU1 - MU2) * ax;
            float muy = (MU1 - MU2) * ay;
            float rho = RHO2 + (RHO1 - RHO2) * aa;
            float g   = sqrtf(ax * ax + ay * ay + EPSC);
            float g3  = g * g * g;
            float curv = -((axx + ayy) / g -
                           (ax * ax * axx + ay * ay * ayy + 2.0f * ax * ay * axy) / g3);
            float oRe  = mu  / RE_DEN;
            float oRex = mux / RE_DEN;
            float oRey = muy / RE_DEN;
            float rr   = rho / RHO_REF;

            float PDE_m = ux + vy;
            float PDE_a = at2 + u * ax + v * ay;
            float PDE_u = (ut + u * ux + v * uy) * rr + p_x - ONE_WE * curv * ax
                        - oRe * (uxx + uyy) - 2.0f * oRex * ux - oRey * (uy + vx);
            float PDE_v = (vt + u * vx + v * vy) * rr + p_y - ONE_WE * curv * ay
                        - oRe * (vxx + vyy) - rr * ONE_FR - 2.0f * oRey * vy - oRex * (uy + vx);

            out[0 * N + n] = PDE_m;
            out[1 * N + n] = PDE_u;
            out[2 * N + n] = PDE_v;
            out[3 * N + n] = PDE_a;
        }
    }
    __syncthreads();
    if (tid == 0) {
        asm volatile("mbarrier.inval.shared.b64 [%0];" :: "r"(smb + MBAR_OFF + 0)  : "memory");
        asm volatile("mbarrier.inval.shared.b64 [%0];" :: "r"(smb + MBAR_OFF + 8)  : "memory");
        asm volatile("mbarrier.inval.shared.b64 [%0];" :: "r"(smb + MBAR_OFF + 16) : "memory");
        asm volatile("mbarrier.inval.shared.b64 [%0];" :: "r"(smb + MBAR_OFF + 24) : "memory");
    }
}

extern "C" void kernel_launch(void* const* d_in, const int* in_sizes, int n_in,
                              void* d_out, int out_size)
{
    const float* x     = (const float*)d_in[0];
    const float* y     = (const float*)d_in[1];
    const float* t     = (const float*)d_in[2];
    const float* W_in  = (const float*)d_in[3];
    const float* b_in  = (const float*)d_in[4];
    const float* W_h   = (const float*)d_in[5];
    const float* b_h   = (const float*)d_in[6];
    const float* W_out = (const float*)d_in[7];
    const float* b_out = (const float*)d_in[8];
    const float* act   = (const float*)d_in[9];
    float* out = (float*)d_out;
    int N = in_sizes[0];

    cudaFuncSetAttribute(pinn_mma_kernel,
                         cudaFuncAttributeMaxDynamicSharedMemorySize, SMEM_BYTES);

    prep_kernel<<<(NHID * NCHUNK * 256 * 32 + 255) / 256, 256>>>(W_h);

    int blocks = (N + SPB - 1) / SPB;
    pinn_mma_kernel<<<blocks, NTHREADS, SMEM_BYTES>>>(
        x, y, t, W_in, b_in, b_h, W_out, b_out, act, out, N);
}

// round 7
// speedup vs baseline: 2.7410x; 1.1009x over previous
#include <cuda_runtime.h>
#include <cuda_bf16.h>
#include <math.h>
#include <stdint.h>

#define HU       250
#define KPAD     256
#define SPB      16          // samples per block -> M = 128 rows
#define NTHREADS 1024        // 32 warps: warp = (stripe 0..7, n-quarter 0..3)
#define NHID     6
#define NCHUNK   8           // k chunks of 32 per layer
#define TOTCH    (NHID*NCHUNK)

// ---- smem layout (relative to 1024-aligned base) ----
#define A0_OFF   0            // A hi: 128 rows x 512B (256 bf16, XOR-swizzled)
#define A1_OFF   65536        // A lo
#define B_OFF    131072       // 2 stages x (hi 16KB + lo 16KB) = 64KB
#define CTRL_OFF 196608
#define MBAR_OFF (CTRL_OFF)            // full[2] at +0,+8 ; empty[2] at +16,+24
#define ZSH_OFF  (CTRL_OFF + 64)
#define SMEM_BYTES (CTRL_OFF + 64 + 2048 + 1024)

// pre-split weight images: [term][layer][chunk][n=256][k=32 swizzled]
__device__ __nv_bfloat16 g_B[2][NHID][NCHUNK][256][32];

// ---------------- helpers ----------------
__device__ __forceinline__ void mbar_init(uint32_t m, uint32_t cnt) {
    asm volatile("mbarrier.init.shared.b64 [%0], %1;" :: "r"(m), "r"(cnt) : "memory");
}
__device__ __forceinline__ void mbar_expect(uint32_t m, uint32_t bytes) {
    asm volatile("mbarrier.arrive.expect_tx.shared.b64 _, [%0], %1;" :: "r"(m), "r"(bytes) : "memory");
}
__device__ __forceinline__ void mbar_arrive(uint32_t m) {
    asm volatile("mbarrier.arrive.shared.b64 _, [%0];" :: "r"(m) : "memory");
}
__device__ __forceinline__ void mbar_wait(uint32_t m, uint32_t ph) {
    asm volatile(
        "{\n\t.reg .pred P1;\n\t"
        "WAIT_LOOP_%=:\n\t"
        "mbarrier.try_wait.parity.acquire.cta.shared::cta.b64 P1, [%0], %1, 0x989680;\n\t"
        "@P1 bra.uni WAIT_DONE_%=;\n\t"
        "bra.uni WAIT_LOOP_%=;\n\t"
        "WAIT_DONE_%=:\n\t}"
        :: "r"(m), "r"(ph) : "memory");
}
__device__ __forceinline__ void bulk_g2s(uint32_t dst, const void* src, uint32_t bytes, uint32_t mbar) {
    asm volatile("cp.async.bulk.shared::cluster.global.mbarrier::complete_tx::bytes [%0], [%1], %2, [%3];"
                 :: "r"(dst), "l"(src), "r"(bytes), "r"(mbar) : "memory");
}
__device__ __forceinline__ void bar_stripe(int id) {
    asm volatile("bar.sync %0, 128;" :: "r"(id) : "memory");
}
__device__ __forceinline__ void ldmx4(uint32_t& r0, uint32_t& r1, uint32_t& r2, uint32_t& r3, uint32_t addr) {
    asm volatile("ldmatrix.sync.aligned.m8n8.x4.shared.b16 {%0,%1,%2,%3}, [%4];"
                 : "=r"(r0), "=r"(r1), "=r"(r2), "=r"(r3) : "r"(addr));
}
__device__ __forceinline__ void mma_bf16(float* d, uint32_t a0, uint32_t a1, uint32_t a2, uint32_t a3,
                                         uint32_t b0, uint32_t b1) {
    asm volatile("mma.sync.aligned.m16n8k16.row.col.f32.bf16.bf16.f32 "
                 "{%0,%1,%2,%3}, {%4,%5,%6,%7}, {%8,%9}, {%0,%1,%2,%3};"
                 : "+f"(d[0]), "+f"(d[1]), "+f"(d[2]), "+f"(d[3])
                 : "r"(a0), "r"(a1), "r"(a2), "r"(a3), "r"(b0), "r"(b1));
}
__device__ __forceinline__ uint32_t pack_bf16x2(float lo, float hi) {
    __nv_bfloat16 a = __float2bfloat16(lo);
    __nv_bfloat16 b = __float2bfloat16(hi);
    return ((uint32_t)*(unsigned short*)&b << 16) | (uint32_t)*(unsigned short*)&a;
}
__device__ __forceinline__ float elemh(int ch, float c, float z, float zvb, float zx, float zy) {
    float f  = tanhf(c * zvb);
    float dd = c * (1.0f - f * f);
    float m2 = -2.0f * c * f;
    float t2 = (ch == 4) ? zx * zx : (ch == 5) ? zy * zy : (ch == 6) ? zy * zx : 0.0f;
    float h  = fmaf(m2 * dd, t2, dd * z);
    if (ch == 0) h = f;
    if (ch == 7) h = 0.0f;
    return h;
}

// ---------------- prep: split + transpose + swizzle W_h ----------------
__global__ void prep_kernel(const float* __restrict__ W_h) {
    int idx = blockIdx.x * blockDim.x + threadIdx.x;
    if (idx >= NHID * NCHUNK * 256 * 32) return;
    int kk = idx & 31;
    int n  = (idx >> 5) & 255;
    int kc = (idx >> 13) & 7;
    int l  = idx >> 16;
    int kg = kc * 32 + kk;
    float w = (n < HU && kg < HU) ? W_h[(l * HU + kg) * HU + n] : 0.0f;
    __nv_bfloat16 hi = __float2bfloat16(w);
    __nv_bfloat16 lo = __float2bfloat16(w - __bfloat162float(hi));
    int u  = kk >> 3;
    int up = u ^ ((n >> 1) & 3);
    int off = up * 8 + (kk & 7);
    g_B[0][l][kc][n][off] = hi;
    g_B[1][l][kc][n][off] = lo;
}

// ---------------- main kernel ----------------
__global__ __launch_bounds__(NTHREADS, 1)
void pinn_mma_kernel(const float* __restrict__ x,
                     const float* __restrict__ y,
                     const float* __restrict__ t,
                     const float* __restrict__ W_in,
                     const float* __restrict__ b_in,
                     const float* __restrict__ b_h,
                     const float* __restrict__ W_out,
                     const float* __restrict__ b_out,
                     const float* __restrict__ act,
                     float* __restrict__ out,
                     int N)
{
    extern __shared__ char smraw[];
    char* sm = (char*)(((uintptr_t)smraw + 1023) & ~(uintptr_t)1023);
    uint32_t smb;
    asm("{ .reg .u64 tmp; cvta.to.shared.u64 tmp, %1; cvt.u32.u64 %0, tmp; }"
        : "=r"(smb) : "l"(sm));

    const int tid = threadIdx.x;
    const int wid = tid >> 5;          // 0..31
    const int lid = tid & 31;
    const int sw  = wid >> 2;          // stripe 0..7
    const int nq  = wid & 3;           // n-quarter 0..3
    const int n0g = blockIdx.x * SPB;

    if (tid == 0) {
        mbar_init(smb + MBAR_OFF + 0,  1);   // full st0
        mbar_init(smb + MBAR_OFF + 8,  1);   // full st1
        mbar_init(smb + MBAR_OFF + 16, 32);  // empty st0
        mbar_init(smb + MBAR_OFF + 24, 32);  // empty st1
    }

    // -------- input layer: fill A0/A1 (bf16 split, swizzled) --------
    {
        const float c0 = 10.0f * __ldg(&act[0]);
        for (int idx = tid; idx < SPB * KPAD; idx += NTHREADS) {
            int s = idx >> 8, n = idx & 255;
            float hv[8] = {0.f, 0.f, 0.f, 0.f, 0.f, 0.f, 0.f, 0.f};
            if (n < HU) {
                int gn = n0g + s;
                float px = 0.f, py = 0.f, pt = 0.f;
                if (gn < N) { px = x[gn]; py = y[gn]; pt = t[gn]; }
                float w0 = __ldg(&W_in[n]);
                float w1 = __ldg(&W_in[HU + n]);
                float w2 = __ldg(&W_in[2 * HU + n]);
                float bj = __ldg(&b_in[n]);
                float z = px * w0 + py * w1 + pt * w2 + bj;
                float f = tanhf(c0 * z);
                float d = c0 * (1.0f - f * f);
                float fx = d * w0, fy = d * w1;
                float m2 = -2.0f * c0 * f;
                hv[0] = f;  hv[1] = fx; hv[2] = fy; hv[3] = d * w2;
                hv[4] = m2 * fx * w0; hv[5] = m2 * fy * w1; hv[6] = m2 * fy * w0;
            }
            #pragma unroll
            for (int c = 0; c < 8; ++c) {
                int row = 8 * s + c;
                uint32_t addr = (uint32_t)(row * 512 + (((n >> 3) ^ (row & 7)) << 4) + (n & 7) * 2);
                float v = hv[c];
                __nv_bfloat16 hi = __float2bfloat16(v);
                *(__nv_bfloat16*)(sm + A0_OFF + addr) = hi;
                *(__nv_bfloat16*)(sm + A1_OFF + addr) = __float2bfloat16(v - __bfloat162float(hi));
            }
        }
    }
    __syncthreads();

    // prologue: fill both stages
    if (tid == 0) {
        #pragma unroll
        for (int st = 0; st < 2; ++st) {
            uint32_t dst = smb + B_OFF + st * 32768;
            mbar_expect(smb + MBAR_OFF + st * 8, 32768);
            bulk_g2s(dst,         &g_B[0][0][st][0][0], 16384, smb + MBAR_OFF + st * 8);
            bulk_g2s(dst + 16384, &g_B[1][0][st][0][0], 16384, smb + MBAR_OFF + st * 8);
        }
    }

    // lane-constant address pieces
    const int arow = 16 * sw + ((lid >> 3) & 1) * 8 + (lid & 7);
    const int bln  = ((lid >> 3) & 1) * 8 + (lid & 7);
    const int khalf = (lid >> 4);
    const int l7    = lid & 7;
    const uint32_t bswz = (uint32_t)((bln >> 1) & 3);
    const uint32_t abase = smb + A0_OFF + (uint32_t)(arow * 512);
    const uint32_t bbase_n = (uint32_t)((nq * 64 + bln) * 64);

    uint32_t ph0 = 0, ph1 = 0;       // consumer full phases
    uint32_t phe0 = 0, phe1 = 0;     // producer empty phases (tid 0 only)

    #pragma unroll 1
    for (int l = 0; l < NHID; ++l) {
        float d[8][4];
        #pragma unroll
        for (int j = 0; j < 8; ++j) {
            d[j][0] = 0.f; d[j][1] = 0.f; d[j][2] = 0.f; d[j][3] = 0.f;
        }

        #pragma unroll 1
        for (int c = 0; c < NCHUNK; ++c) {
            const int ci = l * NCHUNK + c;
            const int st = ci & 1;
            const uint32_t mb_full  = smb + MBAR_OFF + st * 8;
            const uint32_t mb_empty = smb + MBAR_OFF + 16 + st * 8;
            if (st == 0) { mbar_wait(mb_full, ph0); ph0 ^= 1; }
            else         { mbar_wait(mb_full, ph1); ph1 ^= 1; }

            const uint32_t Bst = smb + B_OFF + st * 32768;
            #pragma unroll
            for (int ks = 0; ks < 2; ++ks) {
                int aku = c * 4 + ks * 2 + khalf;
                uint32_t aaddr = abase + (uint32_t)((aku ^ l7) << 4);
                uint32_t a0, a1, a2, a3, e0, e1, e2, e3;
                ldmx4(a0, a1, a2, a3, aaddr);
                ldmx4(e0, e1, e2, e3, aaddr + (A1_OFF - A0_OFF));

                uint32_t u = (uint32_t)(ks * 2 + khalf);
                uint32_t blane = Bst + bbase_n + ((u ^ bswz) << 4);
                #pragma unroll
                for (int j2 = 0; j2 < 4; ++j2) {
                    uint32_t b0, b1, b2, b3;
                    ldmx4(b0, b1, b2, b3, blane + (uint32_t)(j2 * 1024));
                    mma_bf16(d[2 * j2],     a0, a1, a2, a3, b0, b2);
                    mma_bf16(d[2 * j2 + 1], a0, a1, a2, a3, b1, b3);
                    mma_bf16(d[2 * j2],     e0, e1, e2, e3, b0, b2);   // A1*B0
                    mma_bf16(d[2 * j2 + 1], e0, e1, e2, e3, b1, b3);
                    uint32_t c0, c1, c2, c3;
                    ldmx4(c0, c1, c2, c3, blane + 16384u + (uint32_t)(j2 * 1024));
                    mma_bf16(d[2 * j2],     a0, a1, a2, a3, c0, c2);   // A0*B1
                    mma_bf16(d[2 * j2 + 1], a0, a1, a2, a3, c1, c3);
                }
            }
            if (lid == 0) mbar_arrive(mb_empty);
            if (tid == 0 && ci + 2 < TOTCH) {
                if (st == 0) { mbar_wait(mb_empty, phe0); phe0 ^= 1; }
                else         { mbar_wait(mb_empty, phe1); phe1 ^= 1; }
                int ci2 = ci + 2;
                int l2 = ci2 >> 3, c2 = ci2 & 7;
                uint32_t dst = smb + B_OFF + st * 32768;
                mbar_expect(mb_full, 32768);
                bulk_g2s(dst,         &g_B[0][l2][c2][0][0], 16384, mb_full);
                bulk_g2s(dst + 16384, &g_B[1][l2][c2][0][0], 16384, mb_full);
            }
        }

        // -------- epilogue --------
        if (l == NHID - 1) __syncthreads();
        else               bar_stripe(1 + sw);

        const float cl = 10.0f * __ldg(&act[l + 1]);
        const int ch   = lid >> 2;
        const int srcv = lid & 3, srcx = 4 | (lid & 3), srcy = 8 | (lid & 3);
        const int rA = 16 * sw + ch, rB = 16 * sw + 8 + ch;
        const int sA = 2 * sw, sB = 2 * sw + 1;
        float* hsb = (float*)sm;

        #pragma unroll
        for (int j = 0; j < 8; ++j) {
            int n0 = nq * 64 + 8 * j + 2 * (lid & 3);
            float bv0 = 0.f, bv1 = 0.f;
            if (n0 < HU) {
                float2 bb = *(const float2*)&b_h[l * HU + n0];
                bv0 = bb.x; bv1 = bb.y;
            }

            float zv0 = __shfl_sync(0xffffffffu, d[j][0], srcv);
            float zv1 = __shfl_sync(0xffffffffu, d[j][1], srcv);
            float zx0 = __shfl_sync(0xffffffffu, d[j][0], srcx);
            float zx1 = __shfl_sync(0xffffffffu, d[j][1], srcx);
            float zy0 = __shfl_sync(0xffffffffu, d[j][0], srcy);
            float zy1 = __shfl_sync(0xffffffffu, d[j][1], srcy);
            float hA0 = elemh(ch, cl, d[j][0], zv0 + bv0, zx0, zy0);
            float hA1 = elemh(ch, cl, d[j][1], zv1 + bv1, zx1, zy1);

            float wv0 = __shfl_sync(0xffffffffu, d[j][2], srcv);
            float wv1 = __shfl_sync(0xffffffffu, d[j][3], srcv);
            float wx0 = __shfl_sync(0xffffffffu, d[j][2], srcx);
            float wx1 = __shfl_sync(0xffffffffu, d[j][3], srcx);
            float wy0 = __shfl_sync(0xffffffffu, d[j][2], srcy);
            float wy1 = __shfl_sync(0xffffffffu, d[j][3], srcy);
            float hB0 = elemh(ch, cl, d[j][2], wv0 + bv0, wx0, wy0);
            float hB1 = elemh(ch, cl, d[j][3], wv1 + bv1, wx1, wy1);

            if (n0 >= HU)     { hA0 = 0.f; hB0 = 0.f; }
            if (n0 + 1 >= HU) { hA1 = 0.f; hB1 = 0.f; }

            int unit = nq * 8 + j;
            if (l < NHID - 1) {
                uint32_t offA = (uint32_t)(rA * 512 + ((unit ^ (rA & 7)) << 4) + (n0 & 7) * 2);
                uint32_t offB = (uint32_t)(rB * 512 + ((unit ^ (rB & 7)) << 4) + (n0 & 7) * 2);
                float lA0 = hA0 - __bfloat162float(__float2bfloat16(hA0));
                float lA1 = hA1 - __bfloat162float(__float2bfloat16(hA1));
                float lB0 = hB0 - __bfloat162float(__float2bfloat16(hB0));
                float lB1 = hB1 - __bfloat162float(__float2bfloat16(hB1));
                *(uint32_t*)(sm + A0_OFF + offA) = pack_bf16x2(hA0, hA1);
                *(uint32_t*)(sm + A1_OFF + offA) = pack_bf16x2(lA0, lA1);
                *(uint32_t*)(sm + A0_OFF + offB) = pack_bf16x2(hB0, hB1);
                *(uint32_t*)(sm + A1_OFF + offB) = pack_bf16x2(lB0, lB1);
            } else {
                if (n0 < HU) {
                    hsb[(sA * 256 + n0) * 8 + ch] = hA0;
                    hsb[(sB * 256 + n0) * 8 + ch] = hB0;
                }
                if (n0 + 1 < HU) {
                    hsb[(sA * 256 + n0 + 1) * 8 + ch] = hA1;
                    hsb[(sB * 256 + n0 + 1) * 8 + ch] = hB1;
                }
            }
        }
        if (l < NHID - 1) bar_stripe(1 + sw);
    }
    __syncthreads();   // hsb complete

    // -------- output layer: 16 samples x 4 outs x 7 channels --------
    {
        float* hsb = (float*)sm;
        float* zsh = (float*)(sm + ZSH_OFF);
        for (int idx = tid; idx < SPB * 28; idx += NTHREADS) {
            int s = idx / 28, k2 = idx % 28, o = k2 / 7, c = k2 % 7;
            float acc = (c == 0) ? __ldg(&b_out[o]) : 0.f;
            for (int n = 0; n < HU; ++n)
                acc += hsb[(s * 256 + n) * 8 + c] * __ldg(&W_out[n * 4 + o]);
            zsh[(s * 4 + o) * 8 + c] = acc;
        }
    }
    __syncthreads();

    // -------- residual assembly --------
    if (tid < SPB) {
        int s = tid, n = n0g + s;
        if (n < N) {
            float* zsh = (float*)(sm + ZSH_OFF);
            #define Z(o, c) zsh[((s * 4) + (o)) * 8 + (c)]
            float u = Z(0,0), ux = Z(0,1), uy = Z(0,2), ut = Z(0,3), uxx = Z(0,4), uyy = Z(0,5);
            float v = Z(1,0), vx = Z(1,1), vy = Z(1,2), vt = Z(1,3), vxx = Z(1,4), vyy = Z(1,5);
            float pe  = expf(Z(2,0));
            float p_x = pe * Z(2,1);
            float p_y = pe * Z(2,2);
            float z3  = Z(3,0);
            float aa  = 1.0f / (1.0f + expf(-z3));
            float da  = aa * (1.0f - aa);
            float zax = Z(3,1), zay = Z(3,2), zat = Z(3,3);
            float ax = da * zax, ay = da * zay, at2 = da * zat;
            float om = da * (1.0f - 2.0f * aa);
            float axx = om * zax * zax + da * Z(3,4);
            float ayy = om * zay * zay + da * Z(3,5);
            float axy = om * zax * zay + da * Z(3,6);
            #undef Z
            const float MU1 = 1.0f, MU2 = 10.0f;
            const float RHO1 = 100.0f, RHO2 = 1000.0f, RHO_REF = 1000.0f;
            const float ONE_WE = 24.5f / 500.0f;
            const float ONE_FR = 0.49f;
            const float RE_DEN = 500.0f;
            const float EPSC = 2.2204460492503131e-16f;

            float mu  = MU2 + (MU1 - MU2) * aa;
            float mux = (MU1 - MU2) * ax;
            float muy = (MU1 - MU2) * ay;
            float rho = RHO2 + (RHO1 - RHO2) * aa;
            float g   = sqrtf(ax * ax + ay * ay + EPSC);
            float g3  = g * g * g;
            float curv = -((axx + ayy) / g -
                           (ax * ax * axx + ay * ay * ayy + 2.0f * ax * ay * axy) / g3);
            float oRe  = mu  / RE_DEN;
            float oRex = mux / RE_DEN;
            float oRey = muy / RE_DEN;
            float rr   = rho / RHO_REF;

            float PDE_m = ux + vy;
            float PDE_a = at2 + u * ax + v * ay;
            float PDE_u = (ut + u * ux + v * uy) * rr + p_x - ONE_WE * curv * ax
                        - oRe * (uxx + uyy) - 2.0f * oRex * ux - oRey * (uy + vx);
            float PDE_v = (vt + u * vx + v * vy) * rr + p_y - ONE_WE * curv * ay
                        - oRe * (vxx + vyy) - rr * ONE_FR - 2.0f * oRey * vy - oRex * (uy + vx);

            out[0 * N + n] = PDE_m;
            out[1 * N + n] = PDE_u;
            out[2 * N + n] = PDE_v;
            out[3 * N + n] = PDE_a;
        }
    }
    __syncthreads();
    if (tid == 0) {
        asm volatile("mbarrier.inval.shared.b64 [%0];" :: "r"(smb + MBAR_OFF + 0)  : "memory");
        asm volatile("mbarrier.inval.shared.b64 [%0];" :: "r"(smb + MBAR_OFF + 8)  : "memory");
        asm volatile("mbarrier.inval.shared.b64 [%0];" :: "r"(smb + MBAR_OFF + 16) : "memory");
        asm volatile("mbarrier.inval.shared.b64 [%0];" :: "r"(smb + MBAR_OFF + 24) : "memory");
    }
}

extern "C" void kernel_launch(void* const* d_in, const int* in_sizes, int n_in,
                              void* d_out, int out_size)
{
    const float* x     = (const float*)d_in[0];
    const float* y     = (const float*)d_in[1];
    const float* t     = (const float*)d_in[2];
    const float* W_in  = (const float*)d_in[3];
    const float* b_in  = (const float*)d_in[4];
    const float* W_h   = (const float*)d_in[5];
    const float* b_h   = (const float*)d_in[6];
    const float* W_out = (const float*)d_in[7];
    const float* b_out = (const float*)d_in[8];
    const float* act   = (const float*)d_in[9];
    float* out = (float*)d_out;
    int N = in_sizes[0];

    cudaFuncSetAttribute(pinn_mma_kernel,
                         cudaFuncAttributeMaxDynamicSharedMemorySize, SMEM_BYTES);

    prep_kernel<<<(NHID * NCHUNK * 256 * 32 + 255) / 256, 256>>>(W_h);

    int blocks = (N + SPB - 1) / SPB;
    pinn_mma_kernel<<<blocks, NTHREADS, SMEM_BYTES>>>(
        x, y, t, W_in, b_in, b_h, W_out, b_out, act, out, N);
}

// round 8
// speedup vs baseline: 2.7648x; 1.0087x over previous
#include <cuda_runtime.h>
#include <cuda_bf16.h>
#include <math.h>
#include <stdint.h>

#define HU       250
#define KPAD     256
#define SPB      16          // samples per block -> M = 128 rows
#define NTHREADS 1024        // 32 warps: warp = (stripe 0..7, n-quarter 0..3)
#define NHID     6
#define NCHUNK   8           // k chunks of 32 per layer
#define TOTCH    (NHID*NCHUNK)

// ---- smem layout (relative to 1024-aligned base) ----
#define A0_OFF   0            // A hi: 128 rows x 512B (256 bf16, XOR-swizzled)
#define A1_OFF   65536        // A lo
#define B_OFF    131072       // 3 stages x 32KB (hi 16KB + lo 16KB each)
#define CTRL_OFF 229376       // full[3] @ +0,8,16 ; empty[3] @ +24,32,40
#define ZSH_OFF  (B_OFF)      // reuse B stage 0 after mainloop
#define SMEM_BYTES (CTRL_OFF + 64 + 1024)

// pre-split weight images: [layer][chunk][term][n=256][k=32 swizzled] (hi+lo contiguous)
__device__ __nv_bfloat16 g_B[NHID][NCHUNK][2][256][32];

// ---------------- helpers ----------------
__device__ __forceinline__ void mbar_init(uint32_t m, uint32_t cnt) {
    asm volatile("mbarrier.init.shared.b64 [%0], %1;" :: "r"(m), "r"(cnt) : "memory");
}
__device__ __forceinline__ void mbar_expect(uint32_t m, uint32_t bytes) {
    asm volatile("mbarrier.arrive.expect_tx.shared.b64 _, [%0], %1;" :: "r"(m), "r"(bytes) : "memory");
}
__device__ __forceinline__ void mbar_arrive(uint32_t m) {
    asm volatile("mbarrier.arrive.shared.b64 _, [%0];" :: "r"(m) : "memory");
}
__device__ __forceinline__ void mbar_wait(uint32_t m, uint32_t ph) {
    asm volatile(
        "{\n\t.reg .pred P1;\n\t"
        "WAIT_LOOP_%=:\n\t"
        "mbarrier.try_wait.parity.acquire.cta.shared::cta.b64 P1, [%0], %1, 0x989680;\n\t"
        "@P1 bra.uni WAIT_DONE_%=;\n\t"
        "bra.uni WAIT_LOOP_%=;\n\t"
        "WAIT_DONE_%=:\n\t}"
        :: "r"(m), "r"(ph) : "memory");
}
__device__ __forceinline__ void mbar_wait_relaxed(uint32_t m, uint32_t ph) {
    asm volatile(
        "{\n\t.reg .pred P1;\n\t"
        "WAIT_LOOP_%=:\n\t"
        "mbarrier.try_wait.parity.relaxed.cta.shared::cta.b64 P1, [%0], %1, 0x989680;\n\t"
        "@P1 bra.uni WAIT_DONE_%=;\n\t"
        "bra.uni WAIT_LOOP_%=;\n\t"
        "WAIT_DONE_%=:\n\t}"
        :: "r"(m), "r"(ph) : "memory");
}
__device__ __forceinline__ void bulk_g2s(uint32_t dst, const void* src, uint32_t bytes, uint32_t mbar) {
    asm volatile("cp.async.bulk.shared::cluster.global.mbarrier::complete_tx::bytes [%0], [%1], %2, [%3];"
                 :: "r"(dst), "l"(src), "r"(bytes), "r"(mbar) : "memory");
}
__device__ __forceinline__ void bar_stripe(int id) {
    asm volatile("bar.sync %0, 128;" :: "r"(id) : "memory");
}
__device__ __forceinline__ void ldmx4(uint32_t& r0, uint32_t& r1, uint32_t& r2, uint32_t& r3, uint32_t addr) {
    asm volatile("ldmatrix.sync.aligned.m8n8.x4.shared.b16 {%0,%1,%2,%3}, [%4];"
                 : "=r"(r0), "=r"(r1), "=r"(r2), "=r"(r3) : "r"(addr));
}
__device__ __forceinline__ void mma_bf16(float* d, uint32_t a0, uint32_t a1, uint32_t a2, uint32_t a3,
                                         uint32_t b0, uint32_t b1) {
    asm volatile("mma.sync.aligned.m16n8k16.row.col.f32.bf16.bf16.f32 "
                 "{%0,%1,%2,%3}, {%4,%5,%6,%7}, {%8,%9}, {%0,%1,%2,%3};"
                 : "+f"(d[0]), "+f"(d[1]), "+f"(d[2]), "+f"(d[3])
                 : "r"(a0), "r"(a1), "r"(a2), "r"(a3), "r"(b0), "r"(b1));
}
__device__ __forceinline__ uint32_t pack_bf16x2(float lo, float hi) {
    __nv_bfloat16 a = __float2bfloat16(lo);
    __nv_bfloat16 b = __float2bfloat16(hi);
    return ((uint32_t)*(unsigned short*)&b << 16) | (uint32_t)*(unsigned short*)&a;
}
__device__ __forceinline__ float elemh(int ch, float c, float z, float zvb, float zx, float zy) {
    float f  = tanhf(c * zvb);
    float dd = c * (1.0f - f * f);
    float m2 = -2.0f * c * f;
    float t2 = (ch == 4) ? zx * zx : (ch == 5) ? zy * zy : (ch == 6) ? zy * zx : 0.0f;
    float h  = fmaf(m2 * dd, t2, dd * z);
    if (ch == 0) h = f;
    if (ch == 7) h = 0.0f;
    return h;
}

// ---------------- prep: split + transpose + swizzle W_h ----------------
__global__ void prep_kernel(const float* __restrict__ W_h) {
    int idx = blockIdx.x * blockDim.x + threadIdx.x;
    if (idx >= NHID * NCHUNK * 256 * 32) return;
    int kk = idx & 31;
    int n  = (idx >> 5) & 255;
    int kc = (idx >> 13) & 7;
    int l  = idx >> 16;
    int kg = kc * 32 + kk;
    float w = (n < HU && kg < HU) ? W_h[(l * HU + kg) * HU + n] : 0.0f;
    __nv_bfloat16 hi = __float2bfloat16(w);
    __nv_bfloat16 lo = __float2bfloat16(w - __bfloat162float(hi));
    int u  = kk >> 3;
    int up = u ^ ((n >> 1) & 3);
    int off = up * 8 + (kk & 7);
    g_B[l][kc][0][n][off] = hi;
    g_B[l][kc][1][n][off] = lo;
}

// ---------------- main kernel ----------------
__global__ __launch_bounds__(NTHREADS, 1)
void pinn_mma_kernel(const float* __restrict__ x,
                     const float* __restrict__ y,
                     const float* __restrict__ t,
                     const float* __restrict__ W_in,
                     const float* __restrict__ b_in,
                     const float* __restrict__ b_h,
                     const float* __restrict__ W_out,
                     const float* __restrict__ b_out,
                     const float* __restrict__ act,
                     float* __restrict__ out,
                     int N)
{
    extern __shared__ char smraw[];
    char* sm = (char*)(((uintptr_t)smraw + 1023) & ~(uintptr_t)1023);
    uint32_t smb;
    asm("{ .reg .u64 tmp; cvta.to.shared.u64 tmp, %1; cvt.u32.u64 %0, tmp; }"
        : "=r"(smb) : "l"(sm));

    const int tid = threadIdx.x;
    const int wid = tid >> 5;          // 0..31
    const int lid = tid & 31;
    const int sw  = wid >> 2;          // stripe 0..7
    const int nq  = wid & 3;           // n-quarter 0..3
    const int n0g = blockIdx.x * SPB;

    if (tid == 0) {
        #pragma unroll
        for (int s = 0; s < 3; ++s) {
            mbar_init(smb + CTRL_OFF + s * 8, 1);        // full
            mbar_init(smb + CTRL_OFF + 24 + s * 8, 32);  // empty
        }
    }

    // -------- input layer: fill A0/A1 (bf16 split, swizzled) --------
    {
        const float c0 = 10.0f * __ldg(&act[0]);
        for (int idx = tid; idx < SPB * KPAD; idx += NTHREADS) {
            int s = idx >> 8, n = idx & 255;
            float hv[8] = {0.f, 0.f, 0.f, 0.f, 0.f, 0.f, 0.f, 0.f};
            if (n < HU) {
                int gn = n0g + s;
                float px = 0.f, py = 0.f, pt = 0.f;
                if (gn < N) { px = x[gn]; py = y[gn]; pt = t[gn]; }
                float w0 = __ldg(&W_in[n]);
                float w1 = __ldg(&W_in[HU + n]);
                float w2 = __ldg(&W_in[2 * HU + n]);
                float bj = __ldg(&b_in[n]);
                float z = px * w0 + py * w1 + pt * w2 + bj;
                float f = tanhf(c0 * z);
                float d = c0 * (1.0f - f * f);
                float fx = d * w0, fy = d * w1;
                float m2 = -2.0f * c0 * f;
                hv[0] = f;  hv[1] = fx; hv[2] = fy; hv[3] = d * w2;
                hv[4] = m2 * fx * w0; hv[5] = m2 * fy * w1; hv[6] = m2 * fy * w0;
            }
            #pragma unroll
            for (int c = 0; c < 8; ++c) {
                int row = 8 * s + c;
                uint32_t addr = (uint32_t)(row * 512 + (((n >> 3) ^ (row & 7)) << 4) + (n & 7) * 2);
                float v = hv[c];
                __nv_bfloat16 hi = __float2bfloat16(v);
                *(__nv_bfloat16*)(sm + A0_OFF + addr) = hi;
                *(__nv_bfloat16*)(sm + A1_OFF + addr) = __float2bfloat16(v - __bfloat162float(hi));
            }
        }
    }
    __syncthreads();

    // prologue: fill 3 stages with chunks 0,1,2
    if (tid == 0) {
        #pragma unroll
        for (int s = 0; s < 3; ++s) {
            uint32_t dst = smb + B_OFF + s * 32768;
            mbar_expect(smb + CTRL_OFF + s * 8, 32768);
            bulk_g2s(dst, &g_B[0][s][0][0][0], 32768, smb + CTRL_OFF + s * 8);
        }
    }

    // lane-constant address pieces
    const int arow = 16 * sw + ((lid >> 3) & 1) * 8 + (lid & 7);
    const int bln  = ((lid >> 3) & 1) * 8 + (lid & 7);
    const int khalf = (lid >> 4);
    const int l7    = lid & 7;
    const uint32_t bswz = (uint32_t)((bln >> 1) & 3);
    const uint32_t abase = smb + A0_OFF + (uint32_t)(arow * 512);
    const uint32_t bbase_n = (uint32_t)((nq * 64 + bln) * 64);

    #pragma unroll 1
    for (int l = 0; l < NHID; ++l) {
        float d[8][4];
        #pragma unroll
        for (int j = 0; j < 8; ++j) {
            d[j][0] = 0.f; d[j][1] = 0.f; d[j][2] = 0.f; d[j][3] = 0.f;
        }

        #pragma unroll 1
        for (int c = 0; c < NCHUNK; ++c) {
            const int ci = l * NCHUNK + c;
            const int v  = ci / 3;
            const int st = ci - v * 3;
            mbar_wait(smb + CTRL_OFF + st * 8, (uint32_t)(v & 1));

            const uint32_t Bst = smb + B_OFF + st * 32768;
            #pragma unroll
            for (int ks = 0; ks < 2; ++ks) {
                int aku = c * 4 + ks * 2 + khalf;
                uint32_t aaddr = abase + (uint32_t)((aku ^ l7) << 4);
                uint32_t a0, a1, a2, a3, e0, e1, e2, e3;
                ldmx4(a0, a1, a2, a3, aaddr);
                ldmx4(e0, e1, e2, e3, aaddr + (A1_OFF - A0_OFF));

                uint32_t u = (uint32_t)(ks * 2 + khalf);
                uint32_t blane = Bst + bbase_n + ((u ^ bswz) << 4);
                #pragma unroll
                for (int j2 = 0; j2 < 4; ++j2) {
                    uint32_t b0, b1, b2, b3;
                    ldmx4(b0, b1, b2, b3, blane + (uint32_t)(j2 * 1024));
                    mma_bf16(d[2 * j2],     a0, a1, a2, a3, b0, b2);
                    mma_bf16(d[2 * j2 + 1], a0, a1, a2, a3, b1, b3);
                    mma_bf16(d[2 * j2],     e0, e1, e2, e3, b0, b2);   // A1*B0
                    mma_bf16(d[2 * j2 + 1], e0, e1, e2, e3, b1, b3);
                    uint32_t c0, c1, c2, c3;
                    ldmx4(c0, c1, c2, c3, blane + 16384u + (uint32_t)(j2 * 1024));
                    mma_bf16(d[2 * j2],     a0, a1, a2, a3, c0, c2);   // A0*B1
                    mma_bf16(d[2 * j2 + 1], a0, a1, a2, a3, c1, c3);
                }
            }
            if (lid == 0) mbar_arrive(smb + CTRL_OFF + 24 + st * 8);
            // producer: refill chunk ci+2 into stage (ci+2)%3 == (ci-1)%3;
            // requires chunk ci-1 fully consumed -> one-chunk straggler slack.
            if (tid == 0) {
                int cr = ci + 2;
                if (cr >= 3 && cr < TOTCH) {
                    int vr = cr / 3;
                    int sr = cr - vr * 3;
                    mbar_wait_relaxed(smb + CTRL_OFF + 24 + sr * 8, (uint32_t)((vr - 1) & 1));
                    int l2 = cr >> 3, c2 = cr & 7;
                    uint32_t dst = smb + B_OFF + sr * 32768;
                    mbar_expect(smb + CTRL_OFF + sr * 8, 32768);
                    bulk_g2s(dst, &g_B[l2][c2][0][0][0], 32768, smb + CTRL_OFF + sr * 8);
                }
            }
        }

        // -------- epilogue --------
        if (l == NHID - 1) __syncthreads();
        else               bar_stripe(1 + sw);

        const float cl = 10.0f * __ldg(&act[l + 1]);
        const int ch   = lid >> 2;
        const int srcv = lid & 3, srcx = 4 | (lid & 3), srcy = 8 | (lid & 3);
        const int rA = 16 * sw + ch, rB = 16 * sw + 8 + ch;
        const int sA = 2 * sw, sB = 2 * sw + 1;
        float* hsb = (float*)sm;

        #pragma unroll
        for (int j = 0; j < 8; ++j) {
            int n0 = nq * 64 + 8 * j + 2 * (lid & 3);
            float bv0 = 0.f, bv1 = 0.f;
            if (n0 < HU) {
                float2 bb = *(const float2*)&b_h[l * HU + n0];
                bv0 = bb.x; bv1 = bb.y;
            }

            float zv0 = __shfl_sync(0xffffffffu, d[j][0], srcv);
            float zv1 = __shfl_sync(0xffffffffu, d[j][1], srcv);
            float zx0 = __shfl_sync(0xffffffffu, d[j][0], srcx);
            float zx1 = __shfl_sync(0xffffffffu, d[j][1], srcx);
            float zy0 = __shfl_sync(0xffffffffu, d[j][0], srcy);
            float zy1 = __shfl_sync(0xffffffffu, d[j][1], srcy);
            float hA0 = elemh(ch, cl, d[j][0], zv0 + bv0, zx0, zy0);
            float hA1 = elemh(ch, cl, d[j][1], zv1 + bv1, zx1, zy1);

            float wv0 = __shfl_sync(0xffffffffu, d[j][2], srcv);
            float wv1 = __shfl_sync(0xffffffffu, d[j][3], srcv);
            float wx0 = __shfl_sync(0xffffffffu, d[j][2], srcx);
            float wx1 = __shfl_sync(0xffffffffu, d[j][3], srcx);
            float wy0 = __shfl_sync(0xffffffffu, d[j][2], srcy);
            float wy1 = __shfl_sync(0xffffffffu, d[j][3], srcy);
            float hB0 = elemh(ch, cl, d[j][2], wv0 + bv0, wx0, wy0);
            float hB1 = elemh(ch, cl, d[j][3], wv1 + bv1, wx1, wy1);

            if (n0 >= HU)     { hA0 = 0.f; hB0 = 0.f; }
            if (n0 + 1 >= HU) { hA1 = 0.f; hB1 = 0.f; }

            int unit = nq * 8 + j;
            if (l < NHID - 1) {
                uint32_t offA = (uint32_t)(rA * 512 + ((unit ^ (rA & 7)) << 4) + (n0 & 7) * 2);
                uint32_t offB = (uint32_t)(rB * 512 + ((unit ^ (rB & 7)) << 4) + (n0 & 7) * 2);
                float lA0 = hA0 - __bfloat162float(__float2bfloat16(hA0));
                float lA1 = hA1 - __bfloat162float(__float2bfloat16(hA1));
                float lB0 = hB0 - __bfloat162float(__float2bfloat16(hB0));
                float lB1 = hB1 - __bfloat162float(__float2bfloat16(hB1));
                *(uint32_t*)(sm + A0_OFF + offA) = pack_bf16x2(hA0, hA1);
                *(uint32_t*)(sm + A1_OFF + offA) = pack_bf16x2(lA0, lA1);
                *(uint32_t*)(sm + A0_OFF + offB) = pack_bf16x2(hB0, hB1);
                *(uint32_t*)(sm + A1_OFF + offB) = pack_bf16x2(lB0, lB1);
            } else {
                if (n0 < HU) {
                    hsb[(sA * 256 + n0) * 8 + ch] = hA0;
                    hsb[(sB * 256 + n0) * 8 + ch] = hB0;
                }
                if (n0 + 1 < HU) {
                    hsb[(sA * 256 + n0 + 1) * 8 + ch] = hA1;
                    hsb[(sB * 256 + n0 + 1) * 8 + ch] = hB1;
                }
            }
        }
        if (l < NHID - 1) bar_stripe(1 + sw);
    }
    __syncthreads();   // hsb complete

    // -------- output layer: 16 samples x 4 outs x 7 channels --------
    {
        float* hsb = (float*)sm;
        float* zsh = (float*)(sm + ZSH_OFF);
        for (int idx = tid; idx < SPB * 28; idx += NTHREADS) {
            int s = idx / 28, k2 = idx % 28, o = k2 / 7, c = k2 % 7;
            float acc = (c == 0) ? __ldg(&b_out[o]) : 0.f;
            for (int n = 0; n < HU; ++n)
                acc += hsb[(s * 256 + n) * 8 + c] * __ldg(&W_out[n * 4 + o]);
            zsh[(s * 4 + o) * 8 + c] = acc;
        }
    }
    __syncthreads();

    // -------- residual assembly --------
    if (tid < SPB) {
        int s = tid, n = n0g + s;
        if (n < N) {
            float* zsh = (float*)(sm + ZSH_OFF);
            #define Z(o, c) zsh[((s * 4) + (o)) * 8 + (c)]
            float u = Z(0,0), ux = Z(0,1), uy = Z(0,2), ut = Z(0,3), uxx = Z(0,4), uyy = Z(0,5);
            float v = Z(1,0), vx = Z(1,1), vy = Z(1,2), vt = Z(1,3), vxx = Z(1,4), vyy = Z(1,5);
            float pe  = expf(Z(2,0));
            float p_x = pe * Z(2,1);
            float p_y = pe * Z(2,2);
            float z3  = Z(3,0);
            float aa  = 1.0f / (1.0f + expf(-z3));
            float da  = aa * (1.0f - aa);
            float zax = Z(3,1), zay = Z(3,2), zat = Z(3,3);
            float ax = da * zax, ay = da * zay, at2 = da * zat;
            float om = da * (1.0f - 2.0f * aa);
            float axx = om * zax * zax + da * Z(3,4);
            float ayy = om * zay * zay + da * Z(3,5);
            float axy = om * zax * zay + da * Z(3,6);
            #undef Z
            const float MU1 = 1.0f, MU2 = 10.0f;
            const float RHO1 = 100.0f, RHO2 = 1000.0f, RHO_REF = 1000.0f;
            const float ONE_WE = 24.5f / 500.0f;
            const float ONE_FR = 0.49f;
            const float RE_DEN = 500.0f;
            const float EPSC = 2.2204460492503131e-16f;

            float mu  = MU2 + (MU1 - MU2) * aa;
            float mux = (MU1 - MU2) * ax;
            float muy = (MU1 - MU2) * ay;
            float rho = RHO2 + (RHO1 - RHO2) * aa;
            float g   = sqrtf(ax * ax + ay * ay + EPSC);
            float g3  = g * g * g;
            float curv = -((axx + ayy) / g -
                           (ax * ax * axx + ay * ay * ayy + 2.0f * ax * ay * axy) / g3);
            float oRe  = mu  / RE_DEN;
            float oRex = mux / RE_DEN;
            float oRey = muy / RE_DEN;
            float rr   = rho / RHO_REF;

            float PDE_m = ux + vy;
            float PDE_a = at2 + u * ax + v * ay;
            float PDE_u = (ut + u * ux + v * uy) * rr + p_x - ONE_WE * curv * ax
                        - oRe * (uxx + uyy) - 2.0f * oRex * ux - oRey * (uy + vx);
            float PDE_v = (vt + u * vx + v * vy) * rr + p_y - ONE_WE * curv * ay
                        - oRe * (vxx + vyy) - rr * ONE_FR - 2.0f * oRey * vy - oRex * (uy + vx);

            out[0 * N + n] = PDE_m;
            out[1 * N + n] = PDE_u;
            out[2 * N + n] = PDE_v;
            out[3 * N + n] = PDE_a;
        }
    }
    __syncthreads();
    if (tid == 0) {
        #pragma unroll
        for (int s = 0; s < 3; ++s) {
            asm volatile("mbarrier.inval.shared.b64 [%0];" :: "r"(smb + CTRL_OFF + s * 8) : "memory");
            asm volatile("mbarrier.inval.shared.b64 [%0];" :: "r"(smb + CTRL_OFF + 24 + s * 8) : "memory");
        }
    }
}

extern "C" void kernel_launch(void* const* d_in, const int* in_sizes, int n_in,
                              void* d_out, int out_size)
{
    const float* x     = (const float*)d_in[0];
    const float* y     = (const float*)d_in[1];
    const float* t     = (const float*)d_in[2];
    const float* W_in  = (const float*)d_in[3];
    const float* b_in  = (const float*)d_in[4];
    const float* W_h   = (const float*)d_in[5];
    const float* b_h   = (const float*)d_in[6];
    const float* W_out = (const float*)d_in[7];
    const float* b_out = (const float*)d_in[8];
    const float* act   = (const float*)d_in[9];
    float* out = (float*)d_out;
    int N = in_sizes[0];

    cudaFuncSetAttribute(pinn_mma_kernel,
                         cudaFuncAttributeMaxDynamicSharedMemorySize, SMEM_BYTES);

    prep_kernel<<<(NHID * NCHUNK * 256 * 32 + 255) / 256, 256>>>(W_h);

    int blocks = (N + SPB - 1) / SPB;
    pinn_mma_kernel<<<blocks, NTHREADS, SMEM_BYTES>>>(
        x, y, t, W_in, b_in, b_h, W_out, b_out, act, out, N);
}

// round 9
// speedup vs baseline: 2.8866x; 1.0441x over previous
#include <cuda_runtime.h>
#include <cuda_bf16.h>
#include <math.h>
#include <stdint.h>

#define HU       250
#define KPAD     256
#define SPB      16          // samples per block -> M = 128 rows
#define NTHREADS 1024        // 32 warps: warp = (stripe 0..7, n-quarter 0..3)
#define NHID     6
#define NCHUNK   8           // k chunks of 32 per layer
#define TOTCH    (NHID*NCHUNK)

// ---- smem layout (relative to 1024-aligned base) ----
#define A0_OFF   0            // A hi: 128 rows x 512B (256 bf16, XOR-swizzled)
#define A1_OFF   65536        // A lo
#define B_OFF    131072       // 3 stages x 32KB (hi 16KB + lo 16KB each)
#define CTRL_OFF 229376       // full[3] @ +0,8,16 ; cnt[3] @ +32
#define ZSH_OFF  (B_OFF)      // reuse B stage 0 after mainloop
#define SMEM_BYTES (CTRL_OFF + 64 + 1024)

// pre-split weight images: [layer][chunk][term][n=256][k=32 swizzled] (hi+lo contiguous)
__device__ __nv_bfloat16 g_B[NHID][NCHUNK][2][256][32];

// ---------------- helpers ----------------
__device__ __forceinline__ void mbar_init(uint32_t m, uint32_t cnt) {
    asm volatile("mbarrier.init.shared.b64 [%0], %1;" :: "r"(m), "r"(cnt) : "memory");
}
__device__ __forceinline__ void mbar_expect(uint32_t m, uint32_t bytes) {
    asm volatile("mbarrier.arrive.expect_tx.shared.b64 _, [%0], %1;" :: "r"(m), "r"(bytes) : "memory");
}
__device__ __forceinline__ void mbar_wait(uint32_t m, uint32_t ph) {
    asm volatile(
        "{\n\t.reg .pred P1;\n\t"
        "WAIT_LOOP_%=:\n\t"
        "mbarrier.try_wait.parity.acquire.cta.shared::cta.b64 P1, [%0], %1, 0x989680;\n\t"
        "@P1 bra.uni WAIT_DONE_%=;\n\t"
        "bra.uni WAIT_LOOP_%=;\n\t"
        "WAIT_DONE_%=:\n\t}"
        :: "r"(m), "r"(ph) : "memory");
}
__device__ __forceinline__ void bulk_g2s(uint32_t dst, const void* src, uint32_t bytes, uint32_t mbar) {
    asm volatile("cp.async.bulk.shared::cluster.global.mbarrier::complete_tx::bytes [%0], [%1], %2, [%3];"
                 :: "r"(dst), "l"(src), "r"(bytes), "r"(mbar) : "memory");
}
__device__ __forceinline__ void bar_stripe(int id) {
    asm volatile("bar.sync %0, 128;" :: "r"(id) : "memory");
}
__device__ __forceinline__ void ldmx4(uint32_t& r0, uint32_t& r1, uint32_t& r2, uint32_t& r3, uint32_t addr) {
    asm volatile("ldmatrix.sync.aligned.m8n8.x4.shared.b16 {%0,%1,%2,%3}, [%4];"
                 : "=r"(r0), "=r"(r1), "=r"(r2), "=r"(r3) : "r"(addr));
}
__device__ __forceinline__ void mma_bf16(float* d, uint32_t a0, uint32_t a1, uint32_t a2, uint32_t a3,
                                         uint32_t b0, uint32_t b1) {
    asm volatile("mma.sync.aligned.m16n8k16.row.col.f32.bf16.bf16.f32 "
                 "{%0,%1,%2,%3}, {%4,%5,%6,%7}, {%8,%9}, {%0,%1,%2,%3};"
                 : "+f"(d[0]), "+f"(d[1]), "+f"(d[2]), "+f"(d[3])
                 : "r"(a0), "r"(a1), "r"(a2), "r"(a3), "r"(b0), "r"(b1));
}
__device__ __forceinline__ uint32_t pack_bf16x2(float lo, float hi) {
    __nv_bfloat16 a = __float2bfloat16(lo);
    __nv_bfloat16 b = __float2bfloat16(hi);
    return ((uint32_t)*(unsigned short*)&b << 16) | (uint32_t)*(unsigned short*)&a;
}
// h given precomputed f = tanh(c*(z_val+bias)); same fp ops as before
__device__ __forceinline__ float elemh2(int ch, float c, float z, float f, float zx, float zy) {
    float dd = c * (1.0f - f * f);
    float m2 = -2.0f * c * f;
    float t2 = (ch == 4) ? zx * zx : (ch == 5) ? zy * zy : (ch == 6) ? zy * zx : 0.0f;
    float h  = fmaf(m2 * dd, t2, dd * z);
    if (ch == 0) h = f;
    if (ch == 7) h = 0.0f;
    return h;
}

// ---------------- prep: split + transpose + swizzle W_h ----------------
__global__ void prep_kernel(const float* __restrict__ W_h) {
    int idx = blockIdx.x * blockDim.x + threadIdx.x;
    if (idx >= NHID * NCHUNK * 256 * 32) return;
    int kk = idx & 31;
    int n  = (idx >> 5) & 255;
    int kc = (idx >> 13) & 7;
    int l  = idx >> 16;
    int kg = kc * 32 + kk;
    float w = (n < HU && kg < HU) ? W_h[(l * HU + kg) * HU + n] : 0.0f;
    __nv_bfloat16 hi = __float2bfloat16(w);
    __nv_bfloat16 lo = __float2bfloat16(w - __bfloat162float(hi));
    int u  = kk >> 3;
    int up = u ^ ((n >> 1) & 3);
    int off = up * 8 + (kk & 7);
    g_B[l][kc][0][n][off] = hi;
    g_B[l][kc][1][n][off] = lo;
}

// ---------------- main kernel ----------------
__global__ __launch_bounds__(NTHREADS, 1)
void pinn_mma_kernel(const float* __restrict__ x,
                     const float* __restrict__ y,
                     const float* __restrict__ t,
                     const float* __restrict__ W_in,
                     const float* __restrict__ b_in,
                     const float* __restrict__ b_h,
                     const float* __restrict__ W_out,
                     const float* __restrict__ b_out,
                     const float* __restrict__ act,
                     float* __restrict__ out,
                     int N)
{
    extern __shared__ char smraw[];
    char* sm = (char*)(((uintptr_t)smraw + 1023) & ~(uintptr_t)1023);
    uint32_t smb;
    asm("{ .reg .u64 tmp; cvta.to.shared.u64 tmp, %1; cvt.u32.u64 %0, tmp; }"
        : "=r"(smb) : "l"(sm));

    const int tid = threadIdx.x;
    const int wid = tid >> 5;          // 0..31
    const int lid = tid & 31;
    const int sw  = wid >> 2;          // stripe 0..7
    const int nq  = wid & 3;           // n-quarter 0..3
    const int n0g = blockIdx.x * SPB;
    int* cnt_sm = (int*)(sm + CTRL_OFF + 32);

    if (tid == 0) {
        #pragma unroll
        for (int s = 0; s < 3; ++s) {
            mbar_init(smb + CTRL_OFF + s * 8, 1);   // full
            cnt_sm[s] = 0;
        }
    }

    // -------- input layer: fill A0/A1 (bf16 split, swizzled) --------
    {
        const float c0 = 10.0f * __ldg(&act[0]);
        for (int idx = tid; idx < SPB * KPAD; idx += NTHREADS) {
            int s = idx >> 8, n = idx & 255;
            float hv[8] = {0.f, 0.f, 0.f, 0.f, 0.f, 0.f, 0.f, 0.f};
            if (n < HU) {
                int gn = n0g + s;
                float px = 0.f, py = 0.f, pt = 0.f;
                if (gn < N) { px = x[gn]; py = y[gn]; pt = t[gn]; }
                float w0 = __ldg(&W_in[n]);
                float w1 = __ldg(&W_in[HU + n]);
                float w2 = __ldg(&W_in[2 * HU + n]);
                float bj = __ldg(&b_in[n]);
                float z = px * w0 + py * w1 + pt * w2 + bj;
                float f = tanhf(c0 * z);
                float d = c0 * (1.0f - f * f);
                float fx = d * w0, fy = d * w1;
                float m2 = -2.0f * c0 * f;
                hv[0] = f;  hv[1] = fx; hv[2] = fy; hv[3] = d * w2;
                hv[4] = m2 * fx * w0; hv[5] = m2 * fy * w1; hv[6] = m2 * fy * w0;
            }
            #pragma unroll
            for (int c = 0; c < 8; ++c) {
                int row = 8 * s + c;
                uint32_t addr = (uint32_t)(row * 512 + (((n >> 3) ^ (row & 7)) << 4) + (n & 7) * 2);
                float v = hv[c];
                __nv_bfloat16 hi = __float2bfloat16(v);
                *(__nv_bfloat16*)(sm + A0_OFF + addr) = hi;
                *(__nv_bfloat16*)(sm + A1_OFF + addr) = __float2bfloat16(v - __bfloat162float(hi));
            }
        }
    }
    __syncthreads();

    // prologue: fill 3 stages with chunks 0,1,2
    if (tid == 0) {
        #pragma unroll
        for (int s = 0; s < 3; ++s) {
            uint32_t dst = smb + B_OFF + s * 32768;
            mbar_expect(smb + CTRL_OFF + s * 8, 32768);
            bulk_g2s(dst, &g_B[0][s][0][0][0], 32768, smb + CTRL_OFF + s * 8);
        }
    }

    // lane-constant address pieces
    const int arow = 16 * sw + ((lid >> 3) & 1) * 8 + (lid & 7);
    const int bln  = ((lid >> 3) & 1) * 8 + (lid & 7);
    const int khalf = (lid >> 4);
    const int l7    = lid & 7;
    const uint32_t bswz = (uint32_t)((bln >> 1) & 3);
    const uint32_t abase = smb + A0_OFF + (uint32_t)(arow * 512);
    const uint32_t bbase_n = (uint32_t)((nq * 64 + bln) * 64);

    #pragma unroll 1
    for (int l = 0; l < NHID; ++l) {
        float d[8][4];
        #pragma unroll
        for (int j = 0; j < 8; ++j) {
            d[j][0] = 0.f; d[j][1] = 0.f; d[j][2] = 0.f; d[j][3] = 0.f;
        }

        #pragma unroll 1
        for (int c = 0; c < NCHUNK; ++c) {
            const int ci = l * NCHUNK + c;
            const int v  = ci / 3;
            const int st = ci - v * 3;
            mbar_wait(smb + CTRL_OFF + st * 8, (uint32_t)(v & 1));

            const uint32_t Bst = smb + B_OFF + st * 32768;
            #pragma unroll
            for (int ks = 0; ks < 2; ++ks) {
                int aku = c * 4 + ks * 2 + khalf;
                uint32_t aaddr = abase + (uint32_t)((aku ^ l7) << 4);
                uint32_t a0, a1, a2, a3, e0, e1, e2, e3;
                ldmx4(a0, a1, a2, a3, aaddr);
                ldmx4(e0, e1, e2, e3, aaddr + (A1_OFF - A0_OFF));

                uint32_t u = (uint32_t)(ks * 2 + khalf);
                uint32_t blane = Bst + bbase_n + ((u ^ bswz) << 4);
                #pragma unroll
                for (int j2 = 0; j2 < 4; ++j2) {
                    uint32_t b0, b1, b2, b3;
                    ldmx4(b0, b1, b2, b3, blane + (uint32_t)(j2 * 1024));
                    mma_bf16(d[2 * j2],     a0, a1, a2, a3, b0, b2);
                    mma_bf16(d[2 * j2 + 1], a0, a1, a2, a3, b1, b3);
                    mma_bf16(d[2 * j2],     e0, e1, e2, e3, b0, b2);   // A1*B0
                    mma_bf16(d[2 * j2 + 1], e0, e1, e2, e3, b1, b3);
                    uint32_t c0, c1, c2, c3;
                    ldmx4(c0, c1, c2, c3, blane + 16384u + (uint32_t)(j2 * 1024));
                    mma_bf16(d[2 * j2],     a0, a1, a2, a3, c0, c2);   // A0*B1
                    mma_bf16(d[2 * j2 + 1], a0, a1, a2, a3, c1, c3);
                }
            }
            // last-arriver issues the refill for chunk ci+3 into this stage
            if (lid == 0) {
                int old = atomicAdd(&cnt_sm[st], 1);
                if (old == 31) {
                    cnt_sm[st] = 0;
                    int cr = ci + 3;
                    if (cr < TOTCH) {
                        int l2 = cr >> 3, c2 = cr & 7;
                        uint32_t dst = smb + B_OFF + st * 32768;
                        mbar_expect(smb + CTRL_OFF + st * 8, 32768);
                        bulk_g2s(dst, &g_B[l2][c2][0][0][0], 32768, smb + CTRL_OFF + st * 8);
                    }
                }
            }
        }

        // -------- epilogue --------
        if (l == NHID - 1) __syncthreads();
        else               bar_stripe(1 + sw);

        const float cl = 10.0f * __ldg(&act[l + 1]);
        const int ch   = lid >> 2;
        const int lq   = lid & 3;
        const int srcv = lq, srcx = 4 | lq, srcy = 8 | lq;
        const int rA = 16 * sw + ch, rB = 16 * sw + 8 + ch;
        const int sA = 2 * sw, sB = 2 * sw + 1;
        float* hsb = (float*)sm;

        #pragma unroll
        for (int j = 0; j < 8; ++j) {
            int n0 = nq * 64 + 8 * j + 2 * lq;
            float bv0 = 0.f, bv1 = 0.f;
            if (n0 < HU) {
                float2 bb = *(const float2*)&b_h[l * HU + n0];
                bv0 = bb.x; bv1 = bb.y;
            }

            float zv0 = __shfl_sync(0xffffffffu, d[j][0], srcv);
            float zv1 = __shfl_sync(0xffffffffu, d[j][1], srcv);
            float wv0 = __shfl_sync(0xffffffffu, d[j][2], srcv);
            float wv1 = __shfl_sync(0xffffffffu, d[j][3], srcv);

            // one tanh per lane, deduped across the 8 channel-lanes of this quad
            int e = ch & 3;
            float arg = (e == 0) ? (zv0 + bv0) : (e == 1) ? (zv1 + bv1)
                      : (e == 2) ? (wv0 + bv0) : (wv1 + bv1);
            float tres = tanhf(cl * arg);
            float fA0 = __shfl_sync(0xffffffffu, tres, lq);
            float fA1 = __shfl_sync(0xffffffffu, tres, 4  | lq);
            float fB0 = __shfl_sync(0xffffffffu, tres, 8  | lq);
            float fB1 = __shfl_sync(0xffffffffu, tres, 12 | lq);

            float zx0 = __shfl_sync(0xffffffffu, d[j][0], srcx);
            float zx1 = __shfl_sync(0xffffffffu, d[j][1], srcx);
            float zy0 = __shfl_sync(0xffffffffu, d[j][0], srcy);
            float zy1 = __shfl_sync(0xffffffffu, d[j][1], srcy);
            float hA0 = elemh2(ch, cl, d[j][0], fA0, zx0, zy0);
            float hA1 = elemh2(ch, cl, d[j][1], fA1, zx1, zy1);

            float wx0 = __shfl_sync(0xffffffffu, d[j][2], srcx);
            float wx1 = __shfl_sync(0xffffffffu, d[j][3], srcx);
            float wy0 = __shfl_sync(0xffffffffu, d[j][2], srcy);
            float wy1 = __shfl_sync(0xffffffffu, d[j][3], srcy);
            float hB0 = elemh2(ch, cl, d[j][2], fB0, wx0, wy0);
            float hB1 = elemh2(ch, cl, d[j][3], fB1, wx1, wy1);

            if (n0 >= HU)     { hA0 = 0.f; hB0 = 0.f; }
            if (n0 + 1 >= HU) { hA1 = 0.f; hB1 = 0.f; }

            int unit = nq * 8 + j;
            if (l < NHID - 1) {
                uint32_t offA = (uint32_t)(rA * 512 + ((unit ^ (rA & 7)) << 4) + (n0 & 7) * 2);
                uint32_t offB = (uint32_t)(rB * 512 + ((unit ^ (rB & 7)) << 4) + (n0 & 7) * 2);
                float lA0 = hA0 - __bfloat162float(__float2bfloat16(hA0));
                float lA1 = hA1 - __bfloat162float(__float2bfloat16(hA1));
                float lB0 = hB0 - __bfloat162float(__float2bfloat16(hB0));
                float lB1 = hB1 - __bfloat162float(__float2bfloat16(hB1));
                *(uint32_t*)(sm + A0_OFF + offA) = pack_bf16x2(hA0, hA1);
                *(uint32_t*)(sm + A1_OFF + offA) = pack_bf16x2(lA0, lA1);
                *(uint32_t*)(sm + A0_OFF + offB) = pack_bf16x2(hB0, hB1);
                *(uint32_t*)(sm + A1_OFF + offB) = pack_bf16x2(lB0, lB1);
            } else {
                if (n0 < HU) {
                    hsb[(sA * 256 + n0) * 8 + ch] = hA0;
                    hsb[(sB * 256 + n0) * 8 + ch] = hB0;
                }
                if (n0 + 1 < HU) {
                    hsb[(sA * 256 + n0 + 1) * 8 + ch] = hA1;
                    hsb[(sB * 256 + n0 + 1) * 8 + ch] = hB1;
                }
            }
        }
        if (l < NHID - 1) bar_stripe(1 + sw);
    }
    __syncthreads();   // hsb complete

    // -------- output layer: 16 samples x 4 outs x 7 channels --------
    {
        float* hsb = (float*)sm;
        float* zsh = (float*)(sm + ZSH_OFF);
        for (int idx = tid; idx < SPB * 28; idx += NTHREADS) {
            int s = idx / 28, k2 = idx % 28, o = k2 / 7, c = k2 % 7;
            float acc = (c == 0) ? __ldg(&b_out[o]) : 0.f;
            for (int n = 0; n < HU; ++n)
                acc += hsb[(s * 256 + n) * 8 + c] * __ldg(&W_out[n * 4 + o]);
            zsh[(s * 4 + o) * 8 + c] = acc;
        }
    }
    __syncthreads();

    // -------- residual assembly --------
    if (tid < SPB) {
        int s = tid, n = n0g + s;
        if (n < N) {
            float* zsh = (float*)(sm + ZSH_OFF);
            #define Z(o, c) zsh[((s * 4) + (o)) * 8 + (c)]
            float u = Z(0,0), ux = Z(0,1), uy = Z(0,2), ut = Z(0,3), uxx = Z(0,4), uyy = Z(0,5);
            float v = Z(1,0), vx = Z(1,1), vy = Z(1,2), vt = Z(1,3), vxx = Z(1,4), vyy = Z(1,5);
            float pe  = expf(Z(2,0));
            float p_x = pe * Z(2,1);
            float p_y = pe * Z(2,2);
            float z3  = Z(3,0);
            float aa  = 1.0f / (1.0f + expf(-z3));
            float da  = aa * (1.0f - aa);
            float zax = Z(3,1), zay = Z(3,2), zat = Z(3,3);
            float ax = da * zax, ay = da * zay, at2 = da * zat;
            float om = da * (1.0f - 2.0f * aa);
            float axx = om * zax * zax + da * Z(3,4);
            float ayy = om * zay * zay + da * Z(3,5);
            float axy = om * zax * zay + da * Z(3,6);
            #undef Z
            const float MU1 = 1.0f, MU2 = 10.0f;
            const float RHO1 = 100.0f, RHO2 = 1000.0f, RHO_REF = 1000.0f;
            const float ONE_WE = 24.5f / 500.0f;
            const float ONE_FR = 0.49f;
            const float RE_DEN = 500.0f;
            const float EPSC = 2.2204460492503131e-16f;

            float mu  = MU2 + (MU1 - MU2) * aa;
            float mux = (MU1 - MU2) * ax;
            float muy = (MU1 - MU2) * ay;
            float rho = RHO2 + (RHO1 - RHO2) * aa;
            float g   = sqrtf(ax * ax + ay * ay + EPSC);
            float g3  = g * g * g;
            float curv = -((axx + ayy) / g -
                           (ax * ax * axx + ay * ay * ayy + 2.0f * ax * ay * axy) / g3);
            float oRe  = mu  / RE_DEN;
            float oRex = mux / RE_DEN;
            float oRey = muy / RE_DEN;
            float rr   = rho / RHO_REF;

            float PDE_m = ux + vy;
            float PDE_a = at2 + u * ax + v * ay;
            float PDE_u = (ut + u * ux + v * uy) * rr + p_x - ONE_WE * curv * ax
                        - oRe * (uxx + uyy) - 2.0f * oRex * ux - oRey * (uy + vx);
            float PDE_v = (vt + u * vx + v * vy) * rr + p_y - ONE_WE * curv * ay
                        - oRe * (vxx + vyy) - rr * ONE_FR - 2.0f * oRey * vy - oRex * (uy + vx);

            out[0 * N + n] = PDE_m;
            out[1 * N + n] = PDE_u;
            out[2 * N + n] = PDE_v;
            out[3 * N + n] = PDE_a;
        }
    }
    __syncthreads();
    if (tid == 0) {
        #pragma unroll
        for (int s = 0; s < 3; ++s)
            asm volatile("mbarrier.inval.shared.b64 [%0];" :: "r"(smb + CTRL_OFF + s * 8) : "memory");
    }
}

extern "C" void kernel_launch(void* const* d_in, const int* in_sizes, int n_in,
                              void* d_out, int out_size)
{
    const float* x     = (const float*)d_in[0];
    const float* y     = (const float*)d_in[1];
    const float* t     = (const float*)d_in[2];
    const float* W_in  = (const float*)d_in[3];
    const float* b_in  = (const float*)d_in[4];
    const float* W_h   = (const float*)d_in[5];
    const float* b_h   = (const float*)d_in[6];
    const float* W_out = (const float*)d_in[7];
    const float* b_out = (const float*)d_in[8];
    const float* act   = (const float*)d_in[9];
    float* out = (float*)d_out;
    int N = in_sizes[0];

    cudaFuncSetAttribute(pinn_mma_kernel,
                         cudaFuncAttributeMaxDynamicSharedMemorySize, SMEM_BYTES);

    prep_kernel<<<(NHID * NCHUNK * 256 * 32 + 255) / 256, 256>>>(W_h);

    int blocks = (N + SPB - 1) / SPB;
    pinn_mma_kernel<<<blocks, NTHREADS, SMEM_BYTES>>>(
        x, y, t, W_in, b_in, b_h, W_out, b_out, act, out, N);
}